// round 7
// baseline (speedup 1.0000x reference)
#include <cuda_runtime.h>
#include <cuda_fp16.h>
#include <mma.h>
#include <math.h>
#include <stdint.h>

using namespace nvcuda;

// ---------------- problem constants ----------------
#define T_TOK 4096
#define HIDN  2048
#define NH    16
#define NKV   4
#define HD    128
#define FF    8192
#define BATCH 4
#define SEQ   1024
#define GRP   (NH / NKV)
#define KVW   (NKV * HD)          // 512
#define EPSV  1e-6f
#define SCALE 0.08838834764831845f

// ---------------- fp32 scratch ----------------
#define OFF_Q      ((size_t)0)
#define OFF_K      ((size_t)8388608)
#define OFF_SCORES ((size_t)10485760)
#define OFF_X2     ((size_t)77594624)
#define OFF_GATE   ((size_t)85983232)
#define OFF_UP     ((size_t)119537664)
#define SCRATCH_FLOATS ((size_t)153092096)
__device__ float g_scratch[SCRATCH_FLOATS];

// ---------------- fp16 scratch ----------------
#define HW_Q     ((size_t)0)
#define HW_K     ((size_t)4194304)
#define HW_V     ((size_t)5242880)
#define HW_O     ((size_t)6291456)
#define HW_G     ((size_t)10485760)
#define HW_U     ((size_t)27262976)
#define HW_D     ((size_t)44040192)
#define H_H16    ((size_t)60817408)
#define H_Q16    ((size_t)69206016)
#define H_K16    ((size_t)77594624)
#define H_V16    ((size_t)79691776)
#define H_P16    ((size_t)81788928)
#define H_ATTN16 ((size_t)148897792)
#define H_GATE16 ((size_t)157286400)
#define HSCRATCH_HALVES ((size_t)190840832)
__device__ __half g_hscratch[HSCRATCH_HALVES];

// ---------------- GEMM config ----------------
#define BM 128
#define BN 128
#define BK 32
#define HPITCH 40                  // 32 + 8 halves pad
#define HSTAGE (128 * HPITCH)      // 5120 halves per tile stage
#define HPITCH_B 136               // PV B [BK][BN]
#define HSTAGE_B (BK * HPITCH_B)

typedef wmma::fragment<wmma::matrix_a, 16, 16, 16, __half, wmma::row_major> AFragH;
typedef wmma::fragment<wmma::matrix_b, 16, 16, 16, __half, wmma::col_major> BFragHC;
typedef wmma::fragment<wmma::matrix_b, 16, 16, 16, __half, wmma::row_major> BFragHR;
typedef wmma::fragment<wmma::accumulator, 16, 16, 16, float> CFragH;

// ============================================================
// fp16 TN GEMM, 4 warps, warp tile 64x64 (c[4][4]), 2 CTAs/SM.
// C[M,N] = A[M,K] @ B[N,K]^T  (fp32 accum)
// EPI: 0 none, 1 +bias, 2 +res.  HOUT: 0 fp32 C, 1 fp16 C.
// ============================================================
template <int EPI, int HOUT>
__global__ void __launch_bounds__(128, 2)
hgemm_tn(const __half* __restrict__ A, int lda,
         const __half* __restrict__ B, int ldb,
         void* __restrict__ Cv, int ldc, int K,
         const float* __restrict__ bias,
         const float* __restrict__ res)
{
    __shared__ __align__(16) __half smem[4 * HSTAGE];   // 40KB
    __half* sA[2] = { smem,              smem + HSTAGE };
    __half* sB[2] = { smem + 2 * HSTAGE, smem + 3 * HSTAGE };

    const int tid  = threadIdx.x;          // 0..127
    const int wid  = tid >> 5;             // 0..3
    const int lane = tid & 31;
    const int m0 = blockIdx.y * BM;
    const int n0 = blockIdx.x * BN;
    const int wm = wid & 1;                // 64-row slab
    const int wn = wid >> 1;               // 64-col slab

    CFragH c[4][4];
#pragma unroll
    for (int i = 0; i < 4; i++)
#pragma unroll
        for (int j = 0; j < 4; j++) wmma::fill_fragment(c[i][j], 0.f);

    // each thread owns one row of the A tile and one row of the B tile
    const __half* gA = A + (size_t)(m0 + tid) * lda;
    const __half* gB = B + (size_t)(n0 + tid) * ldb;

    uint4 ra[4], rb[4];
#pragma unroll
    for (int u = 0; u < 4; u++) {
        ra[u] = *(const uint4*)(gA + u * 8);
        rb[u] = *(const uint4*)(gB + u * 8);
    }
    {
        __half* a = sA[0] + tid * HPITCH;
        __half* b = sB[0] + tid * HPITCH;
#pragma unroll
        for (int u = 0; u < 4; u++) {
            *(uint4*)(a + u * 8) = ra[u];
            *(uint4*)(b + u * 8) = rb[u];
        }
    }
    __syncthreads();

    const int nt = K / BK;
    for (int t = 0; t < nt; t++) {
        const int cur = t & 1;
        if (t + 1 < nt) {
            const int k0 = (t + 1) * BK;
#pragma unroll
            for (int u = 0; u < 4; u++) {
                ra[u] = *(const uint4*)(gA + k0 + u * 8);
                rb[u] = *(const uint4*)(gB + k0 + u * 8);
            }
        }
#pragma unroll
        for (int ks = 0; ks < BK; ks += 16) {
            AFragH af[4];
            BFragHC bf[4];
#pragma unroll
            for (int i = 0; i < 4; i++)
                wmma::load_matrix_sync(af[i], sA[cur] + (wm * 64 + i * 16) * HPITCH + ks, HPITCH);
#pragma unroll
            for (int j = 0; j < 4; j++)
                wmma::load_matrix_sync(bf[j], sB[cur] + (wn * 64 + j * 16) * HPITCH + ks, HPITCH);
#pragma unroll
            for (int i = 0; i < 4; i++)
#pragma unroll
                for (int j = 0; j < 4; j++)
                    wmma::mma_sync(c[i][j], af[i], bf[j], c[i][j]);
        }
        if (t + 1 < nt) {
            const int nxt = cur ^ 1;
            __half* a = sA[nxt] + tid * HPITCH;
            __half* b = sB[nxt] + tid * HPITCH;
#pragma unroll
            for (int u = 0; u < 4; u++) {
                *(uint4*)(a + u * 8) = ra[u];
                *(uint4*)(b + u * 8) = rb[u];
            }
        }
        __syncthreads();
    }

    // epilogue: per-warp 16x16 staging through smem
    float* stage = reinterpret_cast<float*>(smem) + wid * 256;
    const int r  = lane >> 1;
    const int cq = (lane & 1) << 3;
#pragma unroll
    for (int i = 0; i < 4; i++) {
#pragma unroll
        for (int j = 0; j < 4; j++) {
            wmma::store_matrix_sync(stage, c[i][j], 16, wmma::mem_row_major);
            __syncwarp();
            const size_t row_g = (size_t)(m0 + wm * 64 + i * 16 + r);
            const size_t col_g = (size_t)(n0 + wn * 64 + j * 16 + cq);
            float4 v0 = *(float4*)&stage[r * 16 + cq];
            float4 v1 = *(float4*)&stage[r * 16 + cq + 4];
            if (EPI == 1) {
                float4 b0 = *(const float4*)&bias[col_g];
                float4 b1 = *(const float4*)&bias[col_g + 4];
                v0.x += b0.x; v0.y += b0.y; v0.z += b0.z; v0.w += b0.w;
                v1.x += b1.x; v1.y += b1.y; v1.z += b1.z; v1.w += b1.w;
            }
            if (EPI == 2) {
                float4 r0 = *(const float4*)&res[row_g * ldc + col_g];
                float4 r1 = *(const float4*)&res[row_g * ldc + col_g + 4];
                v0.x += r0.x; v0.y += r0.y; v0.z += r0.z; v0.w += r0.w;
                v1.x += r1.x; v1.y += r1.y; v1.z += r1.z; v1.w += r1.w;
            }
            if (HOUT) {
                __half* C = (__half*)Cv;
                __half2 h[4];
                h[0] = __floats2half2_rn(v0.x, v0.y);
                h[1] = __floats2half2_rn(v0.z, v0.w);
                h[2] = __floats2half2_rn(v1.x, v1.y);
                h[3] = __floats2half2_rn(v1.z, v1.w);
                *(uint4*)&C[row_g * ldc + col_g] = *(uint4*)h;
            } else {
                float* C = (float*)Cv;
                *(float4*)&C[row_g * ldc + col_g] = v0;
                *(float4*)&C[row_g * ldc + col_g + 4] = v1;
            }
            __syncwarp();
        }
    }
}

// ============================================================
// Scores: (q16.k16)*SCALE + mask -> fp32 ; lower-triangle only
// (proven R5 path, unchanged)
// ============================================================
__global__ void __launch_bounds__(256, 2)
hscores(const __half* __restrict__ q, const __half* __restrict__ k,
        const float* __restrict__ mask, float* __restrict__ scores)
{
    if (blockIdx.x > blockIdx.y) return;

    const int z = blockIdx.z;
    const int b = z / NH, h = z % NH, kvh = h / GRP;
    const int m0 = blockIdx.y * BM;
    const int n0 = blockIdx.x * BN;
    const __half* A = q + (size_t)b * SEQ * HIDN + (size_t)h * HD;
    const __half* B = k + (size_t)b * SEQ * KVW + (size_t)kvh * HD;
    const float* M = mask + (size_t)b * SEQ * SEQ;
    float* C = scores + (size_t)z * SEQ * SEQ;

    __shared__ __align__(16) __half smem[4 * HSTAGE];
    __half* sA[2] = { smem,              smem + HSTAGE };
    __half* sB[2] = { smem + 2 * HSTAGE, smem + 3 * HSTAGE };

    const int tid  = threadIdx.x;
    const int wid  = tid >> 5;
    const int lane = tid & 31;
    const int wm = wid & 1, wn = wid >> 1;

    CFragH c[4][2];
#pragma unroll
    for (int i = 0; i < 4; i++)
#pragma unroll
        for (int jj = 0; jj < 2; jj++) wmma::fill_fragment(c[i][jj], 0.f);

    const int row = tid >> 1;
    const int c0  = (tid & 1) << 4;
    const __half* gA = A + (size_t)(m0 + row) * HIDN + c0;
    const __half* gB = B + (size_t)(n0 + row) * KVW + c0;

    uint4 ra0, ra1, rb0, rb1;
    ra0 = *(const uint4*)(gA);
    ra1 = *(const uint4*)(gA + 8);
    rb0 = *(const uint4*)(gB);
    rb1 = *(const uint4*)(gB + 8);
    {
        __half* a = sA[0] + row * HPITCH + c0;
        *(uint4*)a = ra0; *(uint4*)(a + 8) = ra1;
        __half* bb = sB[0] + row * HPITCH + c0;
        *(uint4*)bb = rb0; *(uint4*)(bb + 8) = rb1;
    }
    __syncthreads();

    const int nt = HD / BK;
    for (int t = 0; t < nt; t++) {
        const int cur = t & 1;
        if (t + 1 < nt) {
            const int k0 = (t + 1) * BK;
            ra0 = *(const uint4*)(gA + k0);
            ra1 = *(const uint4*)(gA + k0 + 8);
            rb0 = *(const uint4*)(gB + k0);
            rb1 = *(const uint4*)(gB + k0 + 8);
        }
#pragma unroll
        for (int ks = 0; ks < BK; ks += 16) {
            AFragH af[4];
            BFragHC bf[2];
#pragma unroll
            for (int i = 0; i < 4; i++)
                wmma::load_matrix_sync(af[i], sA[cur] + (wm * 64 + i * 16) * HPITCH + ks, HPITCH);
#pragma unroll
            for (int jj = 0; jj < 2; jj++)
                wmma::load_matrix_sync(bf[jj], sB[cur] + (wn * 32 + jj * 16) * HPITCH + ks, HPITCH);
#pragma unroll
            for (int i = 0; i < 4; i++)
#pragma unroll
                for (int jj = 0; jj < 2; jj++)
                    wmma::mma_sync(c[i][jj], af[i], bf[jj], c[i][jj]);
        }
        if (t + 1 < nt) {
            const int nxt = cur ^ 1;
            __half* a = sA[nxt] + row * HPITCH + c0;
            *(uint4*)a = ra0; *(uint4*)(a + 8) = ra1;
            __half* bb = sB[nxt] + row * HPITCH + c0;
            *(uint4*)bb = rb0; *(uint4*)(bb + 8) = rb1;
        }
        __syncthreads();
    }

    float* stage = reinterpret_cast<float*>(smem) + wid * 256;
    const int r  = lane >> 1;
    const int cq = (lane & 1) << 3;
#pragma unroll
    for (int i = 0; i < 4; i++) {
#pragma unroll
        for (int jj = 0; jj < 2; jj++) {
            wmma::store_matrix_sync(stage, c[i][jj], 16, wmma::mem_row_major);
            __syncwarp();
            const size_t row_g = (size_t)(m0 + wm * 64 + i * 16 + r);
            const size_t col_g = (size_t)(n0 + wn * 32 + jj * 16 + cq);
            float4 v0 = *(float4*)&stage[r * 16 + cq];
            float4 v1 = *(float4*)&stage[r * 16 + cq + 4];
            float4 m0v = *(const float4*)&M[row_g * SEQ + col_g];
            float4 m1v = *(const float4*)&M[row_g * SEQ + col_g + 4];
            v0.x = v0.x * SCALE + m0v.x; v0.y = v0.y * SCALE + m0v.y;
            v0.z = v0.z * SCALE + m0v.z; v0.w = v0.w * SCALE + m0v.w;
            v1.x = v1.x * SCALE + m1v.x; v1.y = v1.y * SCALE + m1v.y;
            v1.z = v1.z * SCALE + m1v.z; v1.w = v1.w * SCALE + m1v.w;
            *(float4*)&C[row_g * SEQ + col_g] = v0;
            *(float4*)&C[row_g * SEQ + col_g + 4] = v1;
            __syncwarp();
        }
    }
}

// ============================================================
// PV (NN, causal-trimmed): attn16 = P16 @ V16 (proven R5 path)
// ============================================================
__global__ void __launch_bounds__(256, 2)
hpv(const __half* __restrict__ p, const __half* __restrict__ v,
    __half* __restrict__ out)
{
    const int z = blockIdx.z;
    const int b = z / NH, h = z % NH, kvh = h / GRP;
    const int m0 = blockIdx.y * BM;
    const __half* A = p + (size_t)z * SEQ * SEQ;
    const __half* B = v + (size_t)b * SEQ * KVW + (size_t)kvh * HD;
    __half* C = out + (size_t)b * SEQ * HIDN + (size_t)h * HD;

    __shared__ __align__(16) __half smem[2 * HSTAGE + 2 * HSTAGE_B];
    __half* sA[2] = { smem,              smem + HSTAGE };
    __half* sB[2] = { smem + 2 * HSTAGE, smem + 2 * HSTAGE + HSTAGE_B };

    const int tid  = threadIdx.x;
    const int wid  = tid >> 5;
    const int lane = tid & 31;
    const int wm = wid & 1, wn = wid >> 1;

    CFragH c[4][2];
#pragma unroll
    for (int i = 0; i < 4; i++)
#pragma unroll
        for (int jj = 0; jj < 2; jj++) wmma::fill_fragment(c[i][jj], 0.f);

    const int row = tid >> 1;
    const int c0  = (tid & 1) << 4;
    const int br  = tid >> 3;
    const int bc  = (tid & 7) << 4;
    const __half* gA = A + (size_t)(m0 + row) * SEQ + c0;

    uint4 ra0, ra1, rb0, rb1;
    ra0 = *(const uint4*)(gA);
    ra1 = *(const uint4*)(gA + 8);
    rb0 = *(const uint4*)(B + (size_t)br * KVW + bc);
    rb1 = *(const uint4*)(B + (size_t)br * KVW + bc + 8);
    {
        __half* a = sA[0] + row * HPITCH + c0;
        *(uint4*)a = ra0; *(uint4*)(a + 8) = ra1;
        __half* bb = sB[0] + br * HPITCH_B + bc;
        *(uint4*)bb = rb0; *(uint4*)(bb + 8) = rb1;
    }
    __syncthreads();

    const int nt = (m0 + BM) / BK;
    for (int t = 0; t < nt; t++) {
        const int cur = t & 1;
        if (t + 1 < nt) {
            const int k0 = (t + 1) * BK;
            ra0 = *(const uint4*)(gA + k0);
            ra1 = *(const uint4*)(gA + k0 + 8);
            rb0 = *(const uint4*)(B + (size_t)(k0 + br) * KVW + bc);
            rb1 = *(const uint4*)(B + (size_t)(k0 + br) * KVW + bc + 8);
        }
#pragma unroll
        for (int ks = 0; ks < BK; ks += 16) {
            AFragH af[4];
            BFragHR bf[2];
#pragma unroll
            for (int i = 0; i < 4; i++)
                wmma::load_matrix_sync(af[i], sA[cur] + (wm * 64 + i * 16) * HPITCH + ks, HPITCH);
#pragma unroll
            for (int jj = 0; jj < 2; jj++)
                wmma::load_matrix_sync(bf[jj], sB[cur] + ks * HPITCH_B + (wn * 32 + jj * 16), HPITCH_B);
#pragma unroll
            for (int i = 0; i < 4; i++)
#pragma unroll
                for (int jj = 0; jj < 2; jj++)
                    wmma::mma_sync(c[i][jj], af[i], bf[jj], c[i][jj]);
        }
        if (t + 1 < nt) {
            const int nxt = cur ^ 1;
            __half* a = sA[nxt] + row * HPITCH + c0;
            *(uint4*)a = ra0; *(uint4*)(a + 8) = ra1;
            __half* bb = sB[nxt] + br * HPITCH_B + bc;
            *(uint4*)bb = rb0; *(uint4*)(bb + 8) = rb1;
        }
        __syncthreads();
    }

    float* stage = reinterpret_cast<float*>(smem) + wid * 256;
    const int r  = lane >> 1;
    const int cq = (lane & 1) << 3;
#pragma unroll
    for (int i = 0; i < 4; i++) {
#pragma unroll
        for (int jj = 0; jj < 2; jj++) {
            wmma::store_matrix_sync(stage, c[i][jj], 16, wmma::mem_row_major);
            __syncwarp();
            const size_t row_g = (size_t)(m0 + wm * 64 + i * 16 + r);
            const size_t col_g = (size_t)(wn * 32 + jj * 16 + cq);
            float4 v0 = *(float4*)&stage[r * 16 + cq];
            float4 v1 = *(float4*)&stage[r * 16 + cq + 4];
            __half2 hh[4];
            hh[0] = __floats2half2_rn(v0.x, v0.y);
            hh[1] = __floats2half2_rn(v0.z, v0.w);
            hh[2] = __floats2half2_rn(v1.x, v1.y);
            hh[3] = __floats2half2_rn(v1.z, v1.w);
            *(uint4*)&C[row_g * HIDN + col_g] = *(uint4*)hh;
            __syncwarp();
        }
    }
}

// ---------------- elementwise / reduction kernels ----------------

__global__ void __launch_bounds__(256)
f2h_kernel(const float* __restrict__ in, __half* __restrict__ out, int n)
{
    int i = (blockIdx.x * blockDim.x + threadIdx.x) * 4;
    int stride = gridDim.x * blockDim.x * 4;
    for (; i < n; i += stride) {
        float4 v = *(const float4*)(in + i);
        __half2 h0 = __floats2half2_rn(v.x, v.y);
        __half2 h1 = __floats2half2_rn(v.z, v.w);
        ((__half2*)(out + i))[0] = h0;
        ((__half2*)(out + i))[1] = h1;
    }
}

__global__ void __launch_bounds__(256)
softmax_kernel(const float* __restrict__ s, __half* __restrict__ p16)
{
    const size_t base = (size_t)blockIdx.x * SEQ;
    const int r = blockIdx.x & (SEQ - 1);
    const int L = ((r >> 7) + 1) << 7;
    const int tid = threadIdx.x;
    __shared__ float red[8];

    float vals[4];
    float mx = -1e30f;
    int cnt = 0;
    for (int idx = tid; idx < L; idx += 256) {
        vals[cnt] = s[base + idx];
        mx = fmaxf(mx, vals[cnt]);
        cnt++;
    }
#pragma unroll
    for (int o = 16; o > 0; o >>= 1) mx = fmaxf(mx, __shfl_xor_sync(0xffffffffu, mx, o));
    if ((tid & 31) == 0) red[tid >> 5] = mx;
    __syncthreads();
    float m2 = fmaxf(fmaxf(fmaxf(red[0], red[1]), fmaxf(red[2], red[3])),
                     fmaxf(fmaxf(red[4], red[5]), fmaxf(red[6], red[7])));
    __syncthreads();

    float sum = 0.f;
    for (int c = 0; c < cnt; c++) {
        vals[c] = expf(vals[c] - m2);
        sum += vals[c];
    }
#pragma unroll
    for (int o = 16; o > 0; o >>= 1) sum += __shfl_xor_sync(0xffffffffu, sum, o);
    if ((tid & 31) == 0) red[tid >> 5] = sum;
    __syncthreads();
    float tot = red[0] + red[1] + red[2] + red[3] + red[4] + red[5] + red[6] + red[7];
    float inv = 1.f / tot;
    int c = 0;
    for (int idx = tid; idx < L; idx += 256, c++)
        p16[base + idx] = __float2half_rn(vals[c] * inv);
}

__global__ void __launch_bounds__(256)
rmsnorm_h_kernel(const float* __restrict__ x, const float* __restrict__ w,
                 __half* __restrict__ out)
{
    const size_t base = (size_t)blockIdx.x * HIDN;
    const int tid = threadIdx.x;
    __shared__ float red[8];

    float v[8];
    float ss = 0.f;
#pragma unroll
    for (int jj = 0; jj < 8; jj++) {
        v[jj] = x[base + tid + jj * 256];
        ss += v[jj] * v[jj];
    }
#pragma unroll
    for (int o = 16; o > 0; o >>= 1) ss += __shfl_xor_sync(0xffffffffu, ss, o);
    if ((tid & 31) == 0) red[tid >> 5] = ss;
    __syncthreads();
    float tot = red[0] + red[1] + red[2] + red[3] + red[4] + red[5] + red[6] + red[7];
    float r = rsqrtf(tot * (1.f / HIDN) + EPSV);
#pragma unroll
    for (int jj = 0; jj < 8; jj++)
        out[base + tid + jj * 256] = __float2half_rn(v[jj] * r * w[tid + jj * 256]);
}

__global__ void __launch_bounds__(128)
head_rms_rope_kernel(const float* __restrict__ buf, const float* __restrict__ w,
                     const float* __restrict__ cs, const float* __restrict__ sn,
                     __half* __restrict__ out16, int nheads)
{
    const int t = blockIdx.x;
    const int h = blockIdx.y;
    const int i = threadIdx.x;
    const size_t idx = (size_t)t * nheads * HD + (size_t)h * HD + i;

    float v = buf[idx];
    float ss = v * v;
#pragma unroll
    for (int o = 16; o > 0; o >>= 1) ss += __shfl_xor_sync(0xffffffffu, ss, o);
    __shared__ float red[4];
    if ((i & 31) == 0) red[i >> 5] = ss;
    __syncthreads();
    float tot = red[0] + red[1] + red[2] + red[3];
    float n = v * rsqrtf(tot * (1.f / HD) + EPSV) * w[i];

    __shared__ float sm[HD];
    sm[i] = n;
    __syncthreads();
    float rot = (i < 64) ? -sm[i + 64] : sm[i - 64];
    out16[idx] = __float2half_rn(n * cs[(size_t)t * HD + i] + rot * sn[(size_t)t * HD + i]);
}

__global__ void __launch_bounds__(256)
silu_mul_h_kernel(const float* __restrict__ g, const float* __restrict__ u,
                  __half* __restrict__ out, size_t n)
{
    size_t i = (size_t)blockIdx.x * blockDim.x + threadIdx.x;
    size_t stride = (size_t)gridDim.x * blockDim.x;
    for (; i < n; i += stride) {
        float gv = g[i];
        out[i] = __float2half_rn(gv / (1.f + expf(-gv)) * u[i]);
    }
}

extern "C" void kernel_launch(void* const* d_in, const int* in_sizes, int n_in,
                              void* d_out, int out_size)
{
    const float* x    = (const float*)d_in[0];
    const float* cosv = (const float*)d_in[1];
    const float* sinv = (const float*)d_in[2];
    const float* mask = (const float*)d_in[3];
    const float* wq   = (const float*)d_in[4];
    const float* bq   = (const float*)d_in[5];
    const float* wk   = (const float*)d_in[6];
    const float* bk   = (const float*)d_in[7];
    const float* wv   = (const float*)d_in[8];
    const float* bv   = (const float*)d_in[9];
    const float* wo   = (const float*)d_in[10];
    const float* qw   = (const float*)d_in[11];
    const float* kw   = (const float*)d_in[12];
    const float* ln1  = (const float*)d_in[13];
    const float* ln2  = (const float*)d_in[14];
    const float* wg   = (const float*)d_in[15];
    const float* wu   = (const float*)d_in[16];
    const float* wd   = (const float*)d_in[17];
    float* out = (float*)d_out;

    float* s = nullptr;
    cudaGetSymbolAddress((void**)&s, g_scratch);
    __half* hs = nullptr;
    cudaGetSymbolAddress((void**)&hs, g_hscratch);

    float* q      = s + OFF_Q;
    float* kbuf   = s + OFF_K;
    float* scores = s + OFF_SCORES;
    float* x2     = s + OFF_X2;
    float* gate   = s + OFF_GATE;
    float* up     = s + OFF_UP;

    __half* hwq = hs + HW_Q;
    __half* hwk = hs + HW_K;
    __half* hwv = hs + HW_V;
    __half* hwo = hs + HW_O;
    __half* hwg = hs + HW_G;
    __half* hwu = hs + HW_U;
    __half* hwd = hs + HW_D;
    __half* h16  = hs + H_H16;
    __half* q16  = hs + H_Q16;
    __half* k16  = hs + H_K16;
    __half* v16  = hs + H_V16;
    __half* p16  = hs + H_P16;
    __half* at16 = hs + H_ATTN16;
    __half* g16  = hs + H_GATE16;

    // 0. weights fp32 -> fp16
    f2h_kernel<<<2048, 256>>>(wq, hwq, HIDN * HIDN);
    f2h_kernel<<<1024, 256>>>(wk, hwk, KVW * HIDN);
    f2h_kernel<<<1024, 256>>>(wv, hwv, KVW * HIDN);
    f2h_kernel<<<2048, 256>>>(wo, hwo, HIDN * HIDN);
    f2h_kernel<<<4096, 256>>>(wg, hwg, FF * HIDN);
    f2h_kernel<<<4096, 256>>>(wu, hwu, FF * HIDN);
    f2h_kernel<<<4096, 256>>>(wd, hwd, HIDN * FF);

    // 1. h16 = rmsnorm(x, ln1)
    rmsnorm_h_kernel<<<T_TOK, 256>>>(x, ln1, h16);

    // 2-4. QKV projections (+bias)
    hgemm_tn<1, 0><<<dim3(HIDN / BN, T_TOK / BM), 128>>>(h16, HIDN, hwq, HIDN, q, HIDN, HIDN, bq, nullptr);
    hgemm_tn<1, 0><<<dim3(KVW  / BN, T_TOK / BM), 128>>>(h16, HIDN, hwk, HIDN, kbuf, KVW, HIDN, bk, nullptr);
    hgemm_tn<1, 1><<<dim3(KVW  / BN, T_TOK / BM), 128>>>(h16, HIDN, hwv, HIDN, v16, KVW, HIDN, bv, nullptr);

    // 5-6. per-head RMS + RoPE -> fp16
    head_rms_rope_kernel<<<dim3(T_TOK, NH),  HD>>>(q,    qw, cosv, sinv, q16, NH);
    head_rms_rope_kernel<<<dim3(T_TOK, NKV), HD>>>(kbuf, kw, cosv, sinv, k16, NKV);

    // 7. scores (lower triangle)
    hscores<<<dim3(SEQ / BN, SEQ / BM, BATCH * NH), 256>>>(q16, k16, mask, scores);

    // 8. softmax -> p16
    softmax_kernel<<<BATCH * NH * SEQ, 256>>>(scores, p16);

    // 9. attn16 = P @ V (causal-trimmed)
    hpv<<<dim3(1, SEQ / BM, BATCH * NH), 256>>>(p16, v16, at16);

    // 10. x2 = x + attn @ wo^T
    hgemm_tn<2, 0><<<dim3(HIDN / BN, T_TOK / BM), 128>>>(at16, HIDN, hwo, HIDN, x2, HIDN, HIDN, nullptr, x);

    // 11. h16 = rmsnorm(x2, ln2)
    rmsnorm_h_kernel<<<T_TOK, 256>>>(x2, ln2, h16);

    // 12-13. gate / up projections
    hgemm_tn<0, 0><<<dim3(FF / BN, T_TOK / BM), 128>>>(h16, HIDN, hwg, HIDN, gate, FF, HIDN, nullptr, nullptr);
    hgemm_tn<0, 0><<<dim3(FF / BN, T_TOK / BM), 128>>>(h16, HIDN, hwu, HIDN, up, FF, HIDN, nullptr, nullptr);

    // 14. g16 = silu(gate) * up
    silu_mul_h_kernel<<<8192, 256>>>(gate, up, g16, (size_t)T_TOK * FF);

    // 15. out = x2 + g16 @ wd^T
    hgemm_tn<2, 0><<<dim3(HIDN / BN, T_TOK / BM), 128>>>(g16, FF, hwd, FF, out, HIDN, FF, nullptr, x2);
}

// round 8
// speedup vs baseline: 1.2128x; 1.2128x over previous
#include <cuda_runtime.h>
#include <cuda_fp16.h>
#include <mma.h>
#include <math.h>
#include <stdint.h>

using namespace nvcuda;

// ---------------- problem constants ----------------
#define T_TOK 4096
#define HIDN  2048
#define NH    16
#define NKV   4
#define HD    128
#define FF    8192
#define BATCH 4
#define SEQ   1024
#define GRP   (NH / NKV)
#define KVW   (NKV * HD)          // 512
#define NQKV  (HIDN + 2 * KVW)    // 3072
#define EPSV  1e-6f
#define SCALE 0.08838834764831845f
#define NEGV  -1000000000.0f

// ---------------- fp32 scratch ----------------
#define OFF_QKV    ((size_t)0)           // 4096*3072
#define OFF_SCORES ((size_t)12582912)    // 64*1024*1024
#define OFF_X2     ((size_t)79691776)    // 4096*2048
#define OFF_BIAS   ((size_t)88080384)    // 3072 (pad 4096)
#define SCRATCH_FLOATS ((size_t)88084480)
__device__ float g_scratch[SCRATCH_FLOATS];

// ---------------- fp16 scratch ----------------
#define HW_QKV   ((size_t)0)             // 3072*2048
#define HW_O     ((size_t)6291456)       // 2048*2048
#define HW_G     ((size_t)10485760)      // 8192*2048
#define HW_U     ((size_t)27262976)
#define HW_D     ((size_t)44040192)
#define H_H16    ((size_t)60817408)      // 4096*2048
#define H_Q16    ((size_t)69206016)      // 4096*2048
#define H_K16    ((size_t)77594624)      // 4096*512
#define H_V16    ((size_t)79691776)      // 4096*512
#define H_P16    ((size_t)81788928)      // 64*1024*1024
#define H_ATTN16 ((size_t)148897792)     // 4096*2048
#define H_G16    ((size_t)157286400)     // 4096*8192
#define H_U16    ((size_t)190840832)     // 4096*8192
#define HSCRATCH_HALVES ((size_t)224395264)
__device__ __half g_hscratch[HSCRATCH_HALVES];

// ---------------- GEMM config (proven R5 core) ----------------
#define BM 128
#define BN 128
#define BK 32
#define HPITCH 40
#define HSTAGE (128 * HPITCH)
#define HPITCH_B 136
#define HSTAGE_B (BK * HPITCH_B)

typedef wmma::fragment<wmma::matrix_a, 16, 16, 16, __half, wmma::row_major> AFragH;
typedef wmma::fragment<wmma::matrix_b, 16, 16, 16, __half, wmma::col_major> BFragHC;
typedef wmma::fragment<wmma::matrix_b, 16, 16, 16, __half, wmma::row_major> BFragHR;
typedef wmma::fragment<wmma::accumulator, 16, 16, 16, float> CFragH;

// ============================================================
// fp16 TN GEMM (R5 core): 256 thr, 8 warps, warp tile 64x32.
// EPI: 0 none, 1 +bias, 2 +res.  HOUT: 0 fp32 C, 1 fp16 C.
// ============================================================
template <int EPI, int HOUT>
__global__ void __launch_bounds__(256, 2)
hgemm_tn(const __half* __restrict__ A, int lda,
         const __half* __restrict__ B, int ldb,
         void* __restrict__ Cv, int ldc, int K,
         const float* __restrict__ bias,
         const float* __restrict__ res)
{
    __shared__ __align__(16) __half smem[4 * HSTAGE];
    __half* sA[2] = { smem,              smem + HSTAGE };
    __half* sB[2] = { smem + 2 * HSTAGE, smem + 3 * HSTAGE };

    const int tid  = threadIdx.x;
    const int wid  = tid >> 5;
    const int lane = tid & 31;
    const int m0 = blockIdx.y * BM;
    const int n0 = blockIdx.x * BN;
    const int wm = wid & 1, wn = wid >> 1;

    CFragH c[4][2];
#pragma unroll
    for (int i = 0; i < 4; i++)
#pragma unroll
        for (int j = 0; j < 2; j++) wmma::fill_fragment(c[i][j], 0.f);

    const int row = tid >> 1;
    const int c0  = (tid & 1) << 4;
    const __half* gA = A + (size_t)(m0 + row) * lda + c0;
    const __half* gB = B + (size_t)(n0 + row) * ldb + c0;

    uint4 ra0, ra1, rb0, rb1;
    ra0 = *(const uint4*)(gA);
    ra1 = *(const uint4*)(gA + 8);
    rb0 = *(const uint4*)(gB);
    rb1 = *(const uint4*)(gB + 8);
    {
        __half* a = sA[0] + row * HPITCH + c0;
        *(uint4*)a = ra0; *(uint4*)(a + 8) = ra1;
        __half* b = sB[0] + row * HPITCH + c0;
        *(uint4*)b = rb0; *(uint4*)(b + 8) = rb1;
    }
    __syncthreads();

    const int nt = K / BK;
    for (int t = 0; t < nt; t++) {
        const int cur = t & 1;
        if (t + 1 < nt) {
            const int k0 = (t + 1) * BK;
            ra0 = *(const uint4*)(gA + k0);
            ra1 = *(const uint4*)(gA + k0 + 8);
            rb0 = *(const uint4*)(gB + k0);
            rb1 = *(const uint4*)(gB + k0 + 8);
        }
#pragma unroll
        for (int ks = 0; ks < BK; ks += 16) {
            AFragH af[4];
            BFragHC bf[2];
#pragma unroll
            for (int i = 0; i < 4; i++)
                wmma::load_matrix_sync(af[i], sA[cur] + (wm * 64 + i * 16) * HPITCH + ks, HPITCH);
#pragma unroll
            for (int j = 0; j < 2; j++)
                wmma::load_matrix_sync(bf[j], sB[cur] + (wn * 32 + j * 16) * HPITCH + ks, HPITCH);
#pragma unroll
            for (int i = 0; i < 4; i++)
#pragma unroll
                for (int j = 0; j < 2; j++)
                    wmma::mma_sync(c[i][j], af[i], bf[j], c[i][j]);
        }
        if (t + 1 < nt) {
            const int nxt = cur ^ 1;
            __half* a = sA[nxt] + row * HPITCH + c0;
            *(uint4*)a = ra0; *(uint4*)(a + 8) = ra1;
            __half* b = sB[nxt] + row * HPITCH + c0;
            *(uint4*)b = rb0; *(uint4*)(b + 8) = rb1;
        }
        __syncthreads();
    }

    float* stage = reinterpret_cast<float*>(smem) + wid * 256;
    const int r  = lane >> 1;
    const int cq = (lane & 1) << 3;
#pragma unroll
    for (int i = 0; i < 4; i++) {
#pragma unroll
        for (int j = 0; j < 2; j++) {
            wmma::store_matrix_sync(stage, c[i][j], 16, wmma::mem_row_major);
            __syncwarp();
            const size_t row_g = (size_t)(m0 + wm * 64 + i * 16 + r);
            const size_t col_g = (size_t)(n0 + wn * 32 + j * 16 + cq);
            float4 v0 = *(float4*)&stage[r * 16 + cq];
            float4 v1 = *(float4*)&stage[r * 16 + cq + 4];
            if (EPI == 1) {
                float4 b0 = *(const float4*)&bias[col_g];
                float4 b1 = *(const float4*)&bias[col_g + 4];
                v0.x += b0.x; v0.y += b0.y; v0.z += b0.z; v0.w += b0.w;
                v1.x += b1.x; v1.y += b1.y; v1.z += b1.z; v1.w += b1.w;
            }
            if (EPI == 2) {
                float4 r0 = *(const float4*)&res[row_g * ldc + col_g];
                float4 r1 = *(const float4*)&res[row_g * ldc + col_g + 4];
                v0.x += r0.x; v0.y += r0.y; v0.z += r0.z; v0.w += r0.w;
                v1.x += r1.x; v1.y += r1.y; v1.z += r1.z; v1.w += r1.w;
            }
            if (HOUT) {
                __half* C = (__half*)Cv;
                __half2 h[4];
                h[0] = __floats2half2_rn(v0.x, v0.y);
                h[1] = __floats2half2_rn(v0.z, v0.w);
                h[2] = __floats2half2_rn(v1.x, v1.y);
                h[3] = __floats2half2_rn(v1.z, v1.w);
                *(uint4*)&C[row_g * ldc + col_g] = *(uint4*)h;
            } else {
                float* C = (float*)Cv;
                *(float4*)&C[row_g * ldc + col_g] = v0;
                *(float4*)&C[row_g * ldc + col_g + 4] = v1;
            }
            __syncwarp();
        }
    }
}

// ============================================================
// Scores: (q16.k16)*SCALE + analytic causal mask -> fp32
// lower-triangle blocks only (R5 core, mask reads removed)
// ============================================================
__global__ void __launch_bounds__(256, 2)
hscores(const __half* __restrict__ q, const __half* __restrict__ k,
        float* __restrict__ scores)
{
    if (blockIdx.x > blockIdx.y) return;

    const int z = blockIdx.z;
    const int b = z / NH, h = z % NH, kvh = h / GRP;
    const int m0 = blockIdx.y * BM;
    const int n0 = blockIdx.x * BN;
    const __half* A = q + (size_t)b * SEQ * HIDN + (size_t)h * HD;
    const __half* B = k + (size_t)b * SEQ * KVW + (size_t)kvh * HD;
    float* C = scores + (size_t)z * SEQ * SEQ;
    const bool diag = (blockIdx.x == blockIdx.y);

    __shared__ __align__(16) __half smem[4 * HSTAGE];
    __half* sA[2] = { smem,              smem + HSTAGE };
    __half* sB[2] = { smem + 2 * HSTAGE, smem + 3 * HSTAGE };

    const int tid  = threadIdx.x;
    const int wid  = tid >> 5;
    const int lane = tid & 31;
    const int wm = wid & 1, wn = wid >> 1;

    CFragH c[4][2];
#pragma unroll
    for (int i = 0; i < 4; i++)
#pragma unroll
        for (int jj = 0; jj < 2; jj++) wmma::fill_fragment(c[i][jj], 0.f);

    const int row = tid >> 1;
    const int c0  = (tid & 1) << 4;
    const __half* gA = A + (size_t)(m0 + row) * HIDN + c0;
    const __half* gB = B + (size_t)(n0 + row) * KVW + c0;

    uint4 ra0, ra1, rb0, rb1;
    ra0 = *(const uint4*)(gA);
    ra1 = *(const uint4*)(gA + 8);
    rb0 = *(const uint4*)(gB);
    rb1 = *(const uint4*)(gB + 8);
    {
        __half* a = sA[0] + row * HPITCH + c0;
        *(uint4*)a = ra0; *(uint4*)(a + 8) = ra1;
        __half* bb = sB[0] + row * HPITCH + c0;
        *(uint4*)bb = rb0; *(uint4*)(bb + 8) = rb1;
    }
    __syncthreads();

    const int nt = HD / BK;
    for (int t = 0; t < nt; t++) {
        const int cur = t & 1;
        if (t + 1 < nt) {
            const int k0 = (t + 1) * BK;
            ra0 = *(const uint4*)(gA + k0);
            ra1 = *(const uint4*)(gA + k0 + 8);
            rb0 = *(const uint4*)(gB + k0);
            rb1 = *(const uint4*)(gB + k0 + 8);
        }
#pragma unroll
        for (int ks = 0; ks < BK; ks += 16) {
            AFragH af[4];
            BFragHC bf[2];
#pragma unroll
            for (int i = 0; i < 4; i++)
                wmma::load_matrix_sync(af[i], sA[cur] + (wm * 64 + i * 16) * HPITCH + ks, HPITCH);
#pragma unroll
            for (int jj = 0; jj < 2; jj++)
                wmma::load_matrix_sync(bf[jj], sB[cur] + (wn * 32 + jj * 16) * HPITCH + ks, HPITCH);
#pragma unroll
            for (int i = 0; i < 4; i++)
#pragma unroll
                for (int jj = 0; jj < 2; jj++)
                    wmma::mma_sync(c[i][jj], af[i], bf[jj], c[i][jj]);
        }
        if (t + 1 < nt) {
            const int nxt = cur ^ 1;
            __half* a = sA[nxt] + row * HPITCH + c0;
            *(uint4*)a = ra0; *(uint4*)(a + 8) = ra1;
            __half* bb = sB[nxt] + row * HPITCH + c0;
            *(uint4*)bb = rb0; *(uint4*)(bb + 8) = rb1;
        }
        __syncthreads();
    }

    float* stage = reinterpret_cast<float*>(smem) + wid * 256;
    const int r  = lane >> 1;
    const int cq = (lane & 1) << 3;
#pragma unroll
    for (int i = 0; i < 4; i++) {
#pragma unroll
        for (int jj = 0; jj < 2; jj++) {
            wmma::store_matrix_sync(stage, c[i][jj], 16, wmma::mem_row_major);
            __syncwarp();
            const size_t row_g = (size_t)(m0 + wm * 64 + i * 16 + r);
            const size_t col_g = (size_t)(n0 + wn * 32 + jj * 16 + cq);
            float4 v0 = *(float4*)&stage[r * 16 + cq];
            float4 v1 = *(float4*)&stage[r * 16 + cq + 4];
            v0.x *= SCALE; v0.y *= SCALE; v0.z *= SCALE; v0.w *= SCALE;
            v1.x *= SCALE; v1.y *= SCALE; v1.z *= SCALE; v1.w *= SCALE;
            if (diag) {
                // analytic causal mask (== mask tensor: 0 if t<=s else -1e9)
                if (col_g + 0 > row_g) v0.x += NEGV;
                if (col_g + 1 > row_g) v0.y += NEGV;
                if (col_g + 2 > row_g) v0.z += NEGV;
                if (col_g + 3 > row_g) v0.w += NEGV;
                if (col_g + 4 > row_g) v1.x += NEGV;
                if (col_g + 5 > row_g) v1.y += NEGV;
                if (col_g + 6 > row_g) v1.z += NEGV;
                if (col_g + 7 > row_g) v1.w += NEGV;
            }
            *(float4*)&C[row_g * SEQ + col_g] = v0;
            *(float4*)&C[row_g * SEQ + col_g + 4] = v1;
            __syncwarp();
        }
    }
}

// ============================================================
// PV (NN, causal-trimmed): attn16 = P16 @ V16 (R5 core)
// ============================================================
__global__ void __launch_bounds__(256, 2)
hpv(const __half* __restrict__ p, const __half* __restrict__ v,
    __half* __restrict__ out)
{
    const int z = blockIdx.z;
    const int b = z / NH, h = z % NH, kvh = h / GRP;
    const int m0 = blockIdx.y * BM;
    const __half* A = p + (size_t)z * SEQ * SEQ;
    const __half* B = v + (size_t)b * SEQ * KVW + (size_t)kvh * HD;
    __half* C = out + (size_t)b * SEQ * HIDN + (size_t)h * HD;

    __shared__ __align__(16) __half smem[2 * HSTAGE + 2 * HSTAGE_B];
    __half* sA[2] = { smem,              smem + HSTAGE };
    __half* sB[2] = { smem + 2 * HSTAGE, smem + 2 * HSTAGE + HSTAGE_B };

    const int tid  = threadIdx.x;
    const int wid  = tid >> 5;
    const int lane = tid & 31;
    const int wm = wid & 1, wn = wid >> 1;

    CFragH c[4][2];
#pragma unroll
    for (int i = 0; i < 4; i++)
#pragma unroll
        for (int jj = 0; jj < 2; jj++) wmma::fill_fragment(c[i][jj], 0.f);

    const int row = tid >> 1;
    const int c0  = (tid & 1) << 4;
    const int br  = tid >> 3;
    const int bc  = (tid & 7) << 4;
    const __half* gA = A + (size_t)(m0 + row) * SEQ + c0;

    uint4 ra0, ra1, rb0, rb1;
    ra0 = *(const uint4*)(gA);
    ra1 = *(const uint4*)(gA + 8);
    rb0 = *(const uint4*)(B + (size_t)br * KVW + bc);
    rb1 = *(const uint4*)(B + (size_t)br * KVW + bc + 8);
    {
        __half* a = sA[0] + row * HPITCH + c0;
        *(uint4*)a = ra0; *(uint4*)(a + 8) = ra1;
        __half* bb = sB[0] + br * HPITCH_B + bc;
        *(uint4*)bb = rb0; *(uint4*)(bb + 8) = rb1;
    }
    __syncthreads();

    const int nt = (m0 + BM) / BK;
    for (int t = 0; t < nt; t++) {
        const int cur = t & 1;
        if (t + 1 < nt) {
            const int k0 = (t + 1) * BK;
            ra0 = *(const uint4*)(gA + k0);
            ra1 = *(const uint4*)(gA + k0 + 8);
            rb0 = *(const uint4*)(B + (size_t)(k0 + br) * KVW + bc);
            rb1 = *(const uint4*)(B + (size_t)(k0 + br) * KVW + bc + 8);
        }
#pragma unroll
        for (int ks = 0; ks < BK; ks += 16) {
            AFragH af[4];
            BFragHR bf[2];
#pragma unroll
            for (int i = 0; i < 4; i++)
                wmma::load_matrix_sync(af[i], sA[cur] + (wm * 64 + i * 16) * HPITCH + ks, HPITCH);
#pragma unroll
            for (int jj = 0; jj < 2; jj++)
                wmma::load_matrix_sync(bf[jj], sB[cur] + ks * HPITCH_B + (wn * 32 + jj * 16), HPITCH_B);
#pragma unroll
            for (int i = 0; i < 4; i++)
#pragma unroll
                for (int jj = 0; jj < 2; jj++)
                    wmma::mma_sync(c[i][jj], af[i], bf[jj], c[i][jj]);
        }
        if (t + 1 < nt) {
            const int nxt = cur ^ 1;
            __half* a = sA[nxt] + row * HPITCH + c0;
            *(uint4*)a = ra0; *(uint4*)(a + 8) = ra1;
            __half* bb = sB[nxt] + br * HPITCH_B + bc;
            *(uint4*)bb = rb0; *(uint4*)(bb + 8) = rb1;
        }
        __syncthreads();
    }

    float* stage = reinterpret_cast<float*>(smem) + wid * 256;
    const int r  = lane >> 1;
    const int cq = (lane & 1) << 3;
#pragma unroll
    for (int i = 0; i < 4; i++) {
#pragma unroll
        for (int jj = 0; jj < 2; jj++) {
            wmma::store_matrix_sync(stage, c[i][jj], 16, wmma::mem_row_major);
            __syncwarp();
            const size_t row_g = (size_t)(m0 + wm * 64 + i * 16 + r);
            const size_t col_g = (size_t)(wn * 32 + jj * 16 + cq);
            float4 v0 = *(float4*)&stage[r * 16 + cq];
            float4 v1 = *(float4*)&stage[r * 16 + cq + 4];
            __half2 hh[4];
            hh[0] = __floats2half2_rn(v0.x, v0.y);
            hh[1] = __floats2half2_rn(v0.z, v0.w);
            hh[2] = __floats2half2_rn(v1.x, v1.y);
            hh[3] = __floats2half2_rn(v1.z, v1.w);
            *(uint4*)&C[row_g * HIDN + col_g] = *(uint4*)hh;
            __syncwarp();
        }
    }
}

// ---------------- elementwise / reduction kernels ----------------

__global__ void __launch_bounds__(256)
f2h_kernel(const float* __restrict__ in, __half* __restrict__ out, int n)
{
    int i = (blockIdx.x * blockDim.x + threadIdx.x) * 4;
    int stride = gridDim.x * blockDim.x * 4;
    for (; i < n; i += stride) {
        float4 v = *(const float4*)(in + i);
        ((__half2*)(out + i))[0] = __floats2half2_rn(v.x, v.y);
        ((__half2*)(out + i))[1] = __floats2half2_rn(v.z, v.w);
    }
}

// concat biases bq|bk|bv -> bias[3072]
__global__ void __launch_bounds__(256)
bias_concat_kernel(const float* __restrict__ bq, const float* __restrict__ bk,
                   const float* __restrict__ bv, float* __restrict__ dst)
{
    int i = blockIdx.x * blockDim.x + threadIdx.x;
    if (i < HIDN) dst[i] = bq[i];
    else if (i < HIDN + KVW) dst[i] = bk[i - HIDN];
    else if (i < NQKV) dst[i] = bv[i - HIDN - KVW];
}

// strided v extract: v16[t*512+j] = half(qkv[t*3072 + 2560 + j])
__global__ void __launch_bounds__(256)
v_extract_kernel(const float* __restrict__ qkv, __half* __restrict__ v16)
{
    int idx = (blockIdx.x * blockDim.x + threadIdx.x) * 4;   // over 4096*512
    if (idx >= T_TOK * KVW) return;
    int t = idx >> 9;
    int j = idx & 511;
    float4 v = *(const float4*)(qkv + (size_t)t * NQKV + HIDN + KVW + j);
    ((__half2*)(v16 + idx))[0] = __floats2half2_rn(v.x, v.y);
    ((__half2*)(v16 + idx))[1] = __floats2half2_rn(v.z, v.w);
}

// length-aware softmax: fp32 in, fp16 out
__global__ void __launch_bounds__(256)
softmax_kernel(const float* __restrict__ s, __half* __restrict__ p16)
{
    const size_t base = (size_t)blockIdx.x * SEQ;
    const int r = blockIdx.x & (SEQ - 1);
    const int L = ((r >> 7) + 1) << 7;
    const int tid = threadIdx.x;
    __shared__ float red[8];

    float vals[4];
    float mx = -1e30f;
    int cnt = 0;
    for (int idx = tid; idx < L; idx += 256) {
        vals[cnt] = s[base + idx];
        mx = fmaxf(mx, vals[cnt]);
        cnt++;
    }
#pragma unroll
    for (int o = 16; o > 0; o >>= 1) mx = fmaxf(mx, __shfl_xor_sync(0xffffffffu, mx, o));
    if ((tid & 31) == 0) red[tid >> 5] = mx;
    __syncthreads();
    float m2 = fmaxf(fmaxf(fmaxf(red[0], red[1]), fmaxf(red[2], red[3])),
                     fmaxf(fmaxf(red[4], red[5]), fmaxf(red[6], red[7])));
    __syncthreads();

    float sum = 0.f;
    for (int c = 0; c < cnt; c++) {
        vals[c] = expf(vals[c] - m2);
        sum += vals[c];
    }
#pragma unroll
    for (int o = 16; o > 0; o >>= 1) sum += __shfl_xor_sync(0xffffffffu, sum, o);
    if ((tid & 31) == 0) red[tid >> 5] = sum;
    __syncthreads();
    float tot = red[0] + red[1] + red[2] + red[3] + red[4] + red[5] + red[6] + red[7];
    float inv = 1.f / tot;
    int c = 0;
    for (int idx = tid; idx < L; idx += 256, c++)
        p16[base + idx] = __float2half_rn(vals[c] * inv);
}

__global__ void __launch_bounds__(256)
rmsnorm_h_kernel(const float* __restrict__ x, const float* __restrict__ w,
                 __half* __restrict__ out)
{
    const size_t base = (size_t)blockIdx.x * HIDN;
    const int tid = threadIdx.x;
    __shared__ float red[8];

    float v[8];
    float ss = 0.f;
#pragma unroll
    for (int jj = 0; jj < 8; jj++) {
        v[jj] = x[base + tid + jj * 256];
        ss += v[jj] * v[jj];
    }
#pragma unroll
    for (int o = 16; o > 0; o >>= 1) ss += __shfl_xor_sync(0xffffffffu, ss, o);
    if ((tid & 31) == 0) red[tid >> 5] = ss;
    __syncthreads();
    float tot = red[0] + red[1] + red[2] + red[3] + red[4] + red[5] + red[6] + red[7];
    float r = rsqrtf(tot * (1.f / HIDN) + EPSV);
#pragma unroll
    for (int jj = 0; jj < 8; jj++)
        out[base + tid + jj * 256] = __float2half_rn(v[jj] * r * w[tid + jj * 256]);
}

// per-head RMS + RoPE: fp32 in (row stride instride, col offset inoff), fp16 out
__global__ void __launch_bounds__(128)
head_rms_rope_kernel(const float* __restrict__ buf, int instride, int inoff,
                     const float* __restrict__ w,
                     const float* __restrict__ cs, const float* __restrict__ sn,
                     __half* __restrict__ out16, int outstride)
{
    const int t = blockIdx.x;
    const int h = blockIdx.y;
    const int i = threadIdx.x;
    const size_t iidx = (size_t)t * instride + inoff + h * HD + i;
    const size_t oidx = (size_t)t * outstride + h * HD + i;

    float v = buf[iidx];
    float ss = v * v;
#pragma unroll
    for (int o = 16; o > 0; o >>= 1) ss += __shfl_xor_sync(0xffffffffu, ss, o);
    __shared__ float red[4];
    if ((i & 31) == 0) red[i >> 5] = ss;
    __syncthreads();
    float tot = red[0] + red[1] + red[2] + red[3];
    float n = v * rsqrtf(tot * (1.f / HD) + EPSV) * w[i];

    __shared__ float sm[HD];
    sm[i] = n;
    __syncthreads();
    float rot = (i < 64) ? -sm[i + 64] : sm[i - 64];
    out16[oidx] = __float2half_rn(n * cs[(size_t)t * HD + i] + rot * sn[(size_t)t * HD + i]);
}

// silu(g)*u, fp16 in, fp16 out (in place on g)
__global__ void __launch_bounds__(256)
silu_mul_h16_kernel(__half2* __restrict__ g, const __half2* __restrict__ u, int n2)
{
    int i = blockIdx.x * blockDim.x + threadIdx.x;
    int stride = gridDim.x * blockDim.x;
    for (; i < n2; i += stride) {
        float2 gf = __half22float2(g[i]);
        float2 uf = __half22float2(u[i]);
        float a = gf.x / (1.f + expf(-gf.x)) * uf.x;
        float b = gf.y / (1.f + expf(-gf.y)) * uf.y;
        g[i] = __floats2half2_rn(a, b);
    }
}

extern "C" void kernel_launch(void* const* d_in, const int* in_sizes, int n_in,
                              void* d_out, int out_size)
{
    const float* x    = (const float*)d_in[0];
    const float* cosv = (const float*)d_in[1];
    const float* sinv = (const float*)d_in[2];
    // d_in[3] = mask (unused: analytic causal mask)
    const float* wq   = (const float*)d_in[4];
    const float* bq   = (const float*)d_in[5];
    const float* wk   = (const float*)d_in[6];
    const float* bk   = (const float*)d_in[7];
    const float* wv   = (const float*)d_in[8];
    const float* bv   = (const float*)d_in[9];
    const float* wo   = (const float*)d_in[10];
    const float* qw   = (const float*)d_in[11];
    const float* kw   = (const float*)d_in[12];
    const float* ln1  = (const float*)d_in[13];
    const float* ln2  = (const float*)d_in[14];
    const float* wg   = (const float*)d_in[15];
    const float* wu   = (const float*)d_in[16];
    const float* wd   = (const float*)d_in[17];
    float* out = (float*)d_out;

    float* s = nullptr;
    cudaGetSymbolAddress((void**)&s, g_scratch);
    __half* hs = nullptr;
    cudaGetSymbolAddress((void**)&hs, g_hscratch);

    float* qkv    = s + OFF_QKV;
    float* scores = s + OFF_SCORES;
    float* x2     = s + OFF_X2;
    float* biasc  = s + OFF_BIAS;

    __half* hwqkv = hs + HW_QKV;
    __half* hwo   = hs + HW_O;
    __half* hwg   = hs + HW_G;
    __half* hwu   = hs + HW_U;
    __half* hwd   = hs + HW_D;
    __half* h16   = hs + H_H16;
    __half* q16   = hs + H_Q16;
    __half* k16   = hs + H_K16;
    __half* v16   = hs + H_V16;
    __half* p16   = hs + H_P16;
    __half* at16  = hs + H_ATTN16;
    __half* g16   = hs + H_G16;
    __half* u16   = hs + H_U16;

    // 0. weights fp32 -> fp16 (QKV concatenated)
    f2h_kernel<<<2048, 256>>>(wq, hwqkv,                  HIDN * HIDN);
    f2h_kernel<<<1024, 256>>>(wk, hwqkv + HIDN * HIDN,    KVW * HIDN);
    f2h_kernel<<<1024, 256>>>(wv, hwqkv + (HIDN + KVW) * HIDN, KVW * HIDN);
    f2h_kernel<<<2048, 256>>>(wo, hwo, HIDN * HIDN);
    f2h_kernel<<<4096, 256>>>(wg, hwg, FF * HIDN);
    f2h_kernel<<<4096, 256>>>(wu, hwu, FF * HIDN);
    f2h_kernel<<<4096, 256>>>(wd, hwd, HIDN * FF);
    bias_concat_kernel<<<12, 256>>>(bq, bk, bv, biasc);

    // 1. h16 = rmsnorm(x, ln1)
    rmsnorm_h_kernel<<<T_TOK, 256>>>(x, ln1, h16);

    // 2. fused QKV projection (+bias): qkv[4096,3072]
    hgemm_tn<1, 0><<<dim3(NQKV / BN, T_TOK / BM), 256>>>(h16, HIDN, hwqkv, HIDN, qkv, NQKV, HIDN, biasc, nullptr);

    // 3-5. per-head RMS + RoPE -> q16/k16 ; extract v16
    head_rms_rope_kernel<<<dim3(T_TOK, NH),  HD>>>(qkv, NQKV, 0,    qw, cosv, sinv, q16, HIDN);
    head_rms_rope_kernel<<<dim3(T_TOK, NKV), HD>>>(qkv, NQKV, HIDN, kw, cosv, sinv, k16, KVW);
    v_extract_kernel<<<(T_TOK * KVW / 4 + 255) / 256, 256>>>(qkv, v16);

    // 6. scores (lower triangle, analytic mask)
    hscores<<<dim3(SEQ / BN, SEQ / BM, BATCH * NH), 256>>>(q16, k16, scores);

    // 7. softmax -> p16
    softmax_kernel<<<BATCH * NH * SEQ, 256>>>(scores, p16);

    // 8. attn16 = P @ V (causal-trimmed)
    hpv<<<dim3(1, SEQ / BM, BATCH * NH), 256>>>(p16, v16, at16);

    // 9. x2 = x + attn @ wo^T
    hgemm_tn<2, 0><<<dim3(HIDN / BN, T_TOK / BM), 256>>>(at16, HIDN, hwo, HIDN, x2, HIDN, HIDN, nullptr, x);

    // 10. h16 = rmsnorm(x2, ln2)
    rmsnorm_h_kernel<<<T_TOK, 256>>>(x2, ln2, h16);

    // 11-12. gate / up projections -> fp16
    hgemm_tn<0, 1><<<dim3(FF / BN, T_TOK / BM), 256>>>(h16, HIDN, hwg, HIDN, g16, FF, HIDN, nullptr, nullptr);
    hgemm_tn<0, 1><<<dim3(FF / BN, T_TOK / BM), 256>>>(h16, HIDN, hwu, HIDN, u16, FF, HIDN, nullptr, nullptr);

    // 13. g16 = silu(g16) * u16 (fp16 in/out)
    silu_mul_h16_kernel<<<8192, 256>>>((__half2*)g16, (const __half2*)u16, T_TOK * FF / 2);

    // 14. out = x2 + g16 @ wd^T
    hgemm_tn<2, 0><<<dim3(HIDN / BN, T_TOK / BM), 256>>>(g16, FF, hwd, FF, out, HIDN, FF, nullptr, x2);
}

// round 9
// speedup vs baseline: 1.5010x; 1.2376x over previous
#include <cuda_runtime.h>
#include <cuda_fp16.h>
#include <mma.h>
#include <math.h>
#include <stdint.h>

using namespace nvcuda;

// ---------------- problem constants ----------------
#define T_TOK 4096
#define HIDN  2048
#define NH    16
#define NKV   4
#define HD    128
#define FF    8192
#define BATCH 4
#define SEQ   1024
#define GRP   (NH / NKV)
#define KVW   (NKV * HD)          // 512
#define NQKV  (HIDN + 2 * KVW)    // 3072
#define EPSV  1e-6f
#define SCALE 0.08838834764831845f
#define NEGV  -1000000000.0f

// ---------------- fp32 scratch ----------------
#define OFF_QKV    ((size_t)0)
#define OFF_SCORES ((size_t)12582912)
#define OFF_X2     ((size_t)79691776)
#define OFF_BIAS   ((size_t)88080384)
#define SCRATCH_FLOATS ((size_t)88084480)
__device__ float g_scratch[SCRATCH_FLOATS];

// ---------------- fp16 scratch ----------------
#define HW_QKV   ((size_t)0)
#define HW_O     ((size_t)6291456)
#define HW_G     ((size_t)10485760)
#define HW_U     ((size_t)27262976)
#define HW_D     ((size_t)44040192)
#define H_H16    ((size_t)60817408)
#define H_Q16    ((size_t)69206016)
#define H_K16    ((size_t)77594624)
#define H_V16    ((size_t)79691776)
#define H_P16    ((size_t)81788928)
#define H_ATTN16 ((size_t)148897792)
#define H_G16    ((size_t)157286400)
#define HSCRATCH_HALVES ((size_t)190840832)
__device__ __half g_hscratch[HSCRATCH_HALVES];

// ---------------- cp.async helpers ----------------
__device__ __forceinline__ void cp16(uint32_t dst, const void* src) {
    asm volatile("cp.async.cg.shared.global [%0], [%1], 16;" :: "r"(dst), "l"(src));
}
__device__ __forceinline__ void cp_commit() {
    asm volatile("cp.async.commit_group;");
}
template <int N>
__device__ __forceinline__ void cp_wait() {
    asm volatile("cp.async.wait_group %0;" :: "n"(N));
}

typedef wmma::fragment<wmma::matrix_a, 16, 16, 16, __half, wmma::row_major> AFragH;
typedef wmma::fragment<wmma::matrix_b, 16, 16, 16, __half, wmma::col_major> BFragHC;
typedef wmma::fragment<wmma::matrix_b, 16, 16, 16, __half, wmma::row_major> BFragHR;
typedef wmma::fragment<wmma::accumulator, 16, 16, 16, float> CFragH;

// ============================================================
// cp.async weight GEMM: 256 thr, 8 warps (64x32 warp tile),
// BK=64, 3 stages, 2 CTAs/SM.  C[M,N] = A[M,K] @ B[N,K]^T.
// EPI: 0 none, 1 +bias, 2 +res(fp32), 3 silu(resH)*acc.
// HOUT: 0 fp32 C, 1 fp16 C.
// ============================================================
#define BKC 64
#define CPITCH 72                       // 64 + 8 halves pad
#define CSTAGE (128 * CPITCH)           // 9216 halves per tile
#define CAS_SMEM_BYTES (3 * 2 * CSTAGE * 2)   // 110592 B

template <int EPI, int HOUT>
__global__ void __launch_bounds__(256, 2)
casgemm_tn(const __half* __restrict__ A, int lda,
           const __half* __restrict__ B, int ldb,
           void* __restrict__ Cv, int ldc, int K,
           const float* __restrict__ bias,
           const float* __restrict__ res,
           const __half* __restrict__ resH)
{
    extern __shared__ __half csmem[];
    const uint32_t sm32 = (uint32_t)__cvta_generic_to_shared(csmem);

    const int tid  = threadIdx.x;
    const int wid  = tid >> 5;
    const int lane = tid & 31;
    const int m0 = blockIdx.y * 128;
    const int n0 = blockIdx.x * 128;
    const int wm = wid & 1, wn = wid >> 1;

    CFragH c[4][2];
#pragma unroll
    for (int i = 0; i < 4; i++)
#pragma unroll
        for (int j = 0; j < 2; j++) wmma::fill_fragment(c[i][j], 0.f);

    const int row   = tid >> 1;          // 0..127
    const int cb    = (tid & 1) << 5;    // 0 or 32 halves
    const __half* gA = A + (size_t)(m0 + row) * lda + cb;
    const __half* gB = B + (size_t)(n0 + row) * ldb + cb;
    // shared dst base (bytes) for this thread within a stage
    const uint32_t tA = sm32 + (uint32_t)(row * CPITCH + cb) * 2u;
    const uint32_t tB = tA + (uint32_t)CSTAGE * 2u;

#define CAS_LOAD(slot, k0) do {                                         \
        const uint32_t _o = (uint32_t)(slot) * (2u * CSTAGE * 2u);      \
        _Pragma("unroll")                                               \
        for (int _u = 0; _u < 4; _u++) {                                \
            cp16(tA + _o + _u * 16u, gA + (k0) + _u * 8);               \
            cp16(tB + _o + _u * 16u, gB + (k0) + _u * 8);               \
        }                                                               \
    } while (0)

    const int nt = K / BKC;              // >= 32 for all uses

    CAS_LOAD(0, 0);      cp_commit();
    CAS_LOAD(1, BKC);    cp_commit();

    for (int t = 0; t < nt; t++) {
        cp_wait<1>();
        __syncthreads();
        if (t + 2 < nt) CAS_LOAD((t + 2) % 3, (t + 2) * BKC);
        cp_commit();

        const __half* sA = csmem + (t % 3) * 2 * CSTAGE;
        const __half* sB = sA + CSTAGE;
#pragma unroll
        for (int ks = 0; ks < BKC; ks += 16) {
            AFragH af[4];
            BFragHC bf[2];
#pragma unroll
            for (int i = 0; i < 4; i++)
                wmma::load_matrix_sync(af[i], sA + (wm * 64 + i * 16) * CPITCH + ks, CPITCH);
#pragma unroll
            for (int j = 0; j < 2; j++)
                wmma::load_matrix_sync(bf[j], sB + (wn * 32 + j * 16) * CPITCH + ks, CPITCH);
#pragma unroll
            for (int i = 0; i < 4; i++)
#pragma unroll
                for (int j = 0; j < 2; j++)
                    wmma::mma_sync(c[i][j], af[i], bf[j], c[i][j]);
        }
    }
    __syncthreads();

    float* stage = reinterpret_cast<float*>(csmem) + wid * 256;
    const int r  = lane >> 1;
    const int cq = (lane & 1) << 3;
#pragma unroll
    for (int i = 0; i < 4; i++) {
#pragma unroll
        for (int j = 0; j < 2; j++) {
            wmma::store_matrix_sync(stage, c[i][j], 16, wmma::mem_row_major);
            __syncwarp();
            const size_t row_g = (size_t)(m0 + wm * 64 + i * 16 + r);
            const size_t col_g = (size_t)(n0 + wn * 32 + j * 16 + cq);
            float4 v0 = *(float4*)&stage[r * 16 + cq];
            float4 v1 = *(float4*)&stage[r * 16 + cq + 4];
            if (EPI == 1) {
                float4 b0 = *(const float4*)&bias[col_g];
                float4 b1 = *(const float4*)&bias[col_g + 4];
                v0.x += b0.x; v0.y += b0.y; v0.z += b0.z; v0.w += b0.w;
                v1.x += b1.x; v1.y += b1.y; v1.z += b1.z; v1.w += b1.w;
            }
            if (EPI == 2) {
                float4 r0 = *(const float4*)&res[row_g * ldc + col_g];
                float4 r1 = *(const float4*)&res[row_g * ldc + col_g + 4];
                v0.x += r0.x; v0.y += r0.y; v0.z += r0.z; v0.w += r0.w;
                v1.x += r1.x; v1.y += r1.y; v1.z += r1.z; v1.w += r1.w;
            }
            if (EPI == 3) {
                // v = silu(g) * v, g fp16 from resH
                uint4 gu = *(const uint4*)&resH[row_g * ldc + col_g];
                __half2* gh = (__half2*)&gu;
                float2 g0 = __half22float2(gh[0]);
                float2 g1 = __half22float2(gh[1]);
                float2 g2 = __half22float2(gh[2]);
                float2 g3 = __half22float2(gh[3]);
                v0.x *= g0.x / (1.f + expf(-g0.x));
                v0.y *= g0.y / (1.f + expf(-g0.y));
                v0.z *= g1.x / (1.f + expf(-g1.x));
                v0.w *= g1.y / (1.f + expf(-g1.y));
                v1.x *= g2.x / (1.f + expf(-g2.x));
                v1.y *= g2.y / (1.f + expf(-g2.y));
                v1.z *= g3.x / (1.f + expf(-g3.x));
                v1.w *= g3.y / (1.f + expf(-g3.y));
            }
            if (HOUT) {
                __half* C = (__half*)Cv;
                __half2 h[4];
                h[0] = __floats2half2_rn(v0.x, v0.y);
                h[1] = __floats2half2_rn(v0.z, v0.w);
                h[2] = __floats2half2_rn(v1.x, v1.y);
                h[3] = __floats2half2_rn(v1.z, v1.w);
                *(uint4*)&C[row_g * ldc + col_g] = *(uint4*)h;
            } else {
                float* C = (float*)Cv;
                *(float4*)&C[row_g * ldc + col_g] = v0;
                *(float4*)&C[row_g * ldc + col_g + 4] = v1;
            }
            __syncwarp();
        }
    }
#undef CAS_LOAD
}

// ============================================================
// Attention kernels (R8-proven, unchanged)
// ============================================================
#define BM 128
#define BN 128
#define BK 32
#define HPITCH 40
#define HSTAGE (128 * HPITCH)
#define HPITCH_B 136
#define HSTAGE_B (BK * HPITCH_B)

__global__ void __launch_bounds__(256, 2)
hscores(const __half* __restrict__ q, const __half* __restrict__ k,
        float* __restrict__ scores)
{
    if (blockIdx.x > blockIdx.y) return;

    const int z = blockIdx.z;
    const int b = z / NH, h = z % NH, kvh = h / GRP;
    const int m0 = blockIdx.y * BM;
    const int n0 = blockIdx.x * BN;
    const __half* A = q + (size_t)b * SEQ * HIDN + (size_t)h * HD;
    const __half* B = k + (size_t)b * SEQ * KVW + (size_t)kvh * HD;
    float* C = scores + (size_t)z * SEQ * SEQ;
    const bool diag = (blockIdx.x == blockIdx.y);

    __shared__ __align__(16) __half smem[4 * HSTAGE];
    __half* sA[2] = { smem,              smem + HSTAGE };
    __half* sB[2] = { smem + 2 * HSTAGE, smem + 3 * HSTAGE };

    const int tid  = threadIdx.x;
    const int wid  = tid >> 5;
    const int lane = tid & 31;
    const int wm = wid & 1, wn = wid >> 1;

    CFragH c[4][2];
#pragma unroll
    for (int i = 0; i < 4; i++)
#pragma unroll
        for (int jj = 0; jj < 2; jj++) wmma::fill_fragment(c[i][jj], 0.f);

    const int row = tid >> 1;
    const int c0  = (tid & 1) << 4;
    const __half* gA = A + (size_t)(m0 + row) * HIDN + c0;
    const __half* gB = B + (size_t)(n0 + row) * KVW + c0;

    uint4 ra0, ra1, rb0, rb1;
    ra0 = *(const uint4*)(gA);
    ra1 = *(const uint4*)(gA + 8);
    rb0 = *(const uint4*)(gB);
    rb1 = *(const uint4*)(gB + 8);
    {
        __half* a = sA[0] + row * HPITCH + c0;
        *(uint4*)a = ra0; *(uint4*)(a + 8) = ra1;
        __half* bb = sB[0] + row * HPITCH + c0;
        *(uint4*)bb = rb0; *(uint4*)(bb + 8) = rb1;
    }
    __syncthreads();

    const int nt = HD / BK;
    for (int t = 0; t < nt; t++) {
        const int cur = t & 1;
        if (t + 1 < nt) {
            const int k0 = (t + 1) * BK;
            ra0 = *(const uint4*)(gA + k0);
            ra1 = *(const uint4*)(gA + k0 + 8);
            rb0 = *(const uint4*)(gB + k0);
            rb1 = *(const uint4*)(gB + k0 + 8);
        }
#pragma unroll
        for (int ks = 0; ks < BK; ks += 16) {
            AFragH af[4];
            BFragHC bf[2];
#pragma unroll
            for (int i = 0; i < 4; i++)
                wmma::load_matrix_sync(af[i], sA[cur] + (wm * 64 + i * 16) * HPITCH + ks, HPITCH);
#pragma unroll
            for (int jj = 0; jj < 2; jj++)
                wmma::load_matrix_sync(bf[jj], sB[cur] + (wn * 32 + jj * 16) * HPITCH + ks, HPITCH);
#pragma unroll
            for (int i = 0; i < 4; i++)
#pragma unroll
                for (int jj = 0; jj < 2; jj++)
                    wmma::mma_sync(c[i][jj], af[i], bf[jj], c[i][jj]);
        }
        if (t + 1 < nt) {
            const int nxt = cur ^ 1;
            __half* a = sA[nxt] + row * HPITCH + c0;
            *(uint4*)a = ra0; *(uint4*)(a + 8) = ra1;
            __half* bb = sB[nxt] + row * HPITCH + c0;
            *(uint4*)bb = rb0; *(uint4*)(bb + 8) = rb1;
        }
        __syncthreads();
    }

    float* stage = reinterpret_cast<float*>(smem) + wid * 256;
    const int r  = lane >> 1;
    const int cq = (lane & 1) << 3;
#pragma unroll
    for (int i = 0; i < 4; i++) {
#pragma unroll
        for (int jj = 0; jj < 2; jj++) {
            wmma::store_matrix_sync(stage, c[i][jj], 16, wmma::mem_row_major);
            __syncwarp();
            const size_t row_g = (size_t)(m0 + wm * 64 + i * 16 + r);
            const size_t col_g = (size_t)(n0 + wn * 32 + jj * 16 + cq);
            float4 v0 = *(float4*)&stage[r * 16 + cq];
            float4 v1 = *(float4*)&stage[r * 16 + cq + 4];
            v0.x *= SCALE; v0.y *= SCALE; v0.z *= SCALE; v0.w *= SCALE;
            v1.x *= SCALE; v1.y *= SCALE; v1.z *= SCALE; v1.w *= SCALE;
            if (diag) {
                if (col_g + 0 > row_g) v0.x += NEGV;
                if (col_g + 1 > row_g) v0.y += NEGV;
                if (col_g + 2 > row_g) v0.z += NEGV;
                if (col_g + 3 > row_g) v0.w += NEGV;
                if (col_g + 4 > row_g) v1.x += NEGV;
                if (col_g + 5 > row_g) v1.y += NEGV;
                if (col_g + 6 > row_g) v1.z += NEGV;
                if (col_g + 7 > row_g) v1.w += NEGV;
            }
            *(float4*)&C[row_g * SEQ + col_g] = v0;
            *(float4*)&C[row_g * SEQ + col_g + 4] = v1;
            __syncwarp();
        }
    }
}

__global__ void __launch_bounds__(256, 2)
hpv(const __half* __restrict__ p, const __half* __restrict__ v,
    __half* __restrict__ out)
{
    const int z = blockIdx.z;
    const int b = z / NH, h = z % NH, kvh = h / GRP;
    const int m0 = blockIdx.y * BM;
    const __half* A = p + (size_t)z * SEQ * SEQ;
    const __half* B = v + (size_t)b * SEQ * KVW + (size_t)kvh * HD;
    __half* C = out + (size_t)b * SEQ * HIDN + (size_t)h * HD;

    __shared__ __align__(16) __half smem[2 * HSTAGE + 2 * HSTAGE_B];
    __half* sA[2] = { smem,              smem + HSTAGE };
    __half* sB[2] = { smem + 2 * HSTAGE, smem + 2 * HSTAGE + HSTAGE_B };

    const int tid  = threadIdx.x;
    const int wid  = tid >> 5;
    const int lane = tid & 31;
    const int wm = wid & 1, wn = wid >> 1;

    CFragH c[4][2];
#pragma unroll
    for (int i = 0; i < 4; i++)
#pragma unroll
        for (int jj = 0; jj < 2; jj++) wmma::fill_fragment(c[i][jj], 0.f);

    const int row = tid >> 1;
    const int c0  = (tid & 1) << 4;
    const int br  = tid >> 3;
    const int bc  = (tid & 7) << 4;
    const __half* gA = A + (size_t)(m0 + row) * SEQ + c0;

    uint4 ra0, ra1, rb0, rb1;
    ra0 = *(const uint4*)(gA);
    ra1 = *(const uint4*)(gA + 8);
    rb0 = *(const uint4*)(B + (size_t)br * KVW + bc);
    rb1 = *(const uint4*)(B + (size_t)br * KVW + bc + 8);
    {
        __half* a = sA[0] + row * HPITCH + c0;
        *(uint4*)a = ra0; *(uint4*)(a + 8) = ra1;
        __half* bb = sB[0] + br * HPITCH_B + bc;
        *(uint4*)bb = rb0; *(uint4*)(bb + 8) = rb1;
    }
    __syncthreads();

    const int nt = (m0 + BM) / BK;
    for (int t = 0; t < nt; t++) {
        const int cur = t & 1;
        if (t + 1 < nt) {
            const int k0 = (t + 1) * BK;
            ra0 = *(const uint4*)(gA + k0);
            ra1 = *(const uint4*)(gA + k0 + 8);
            rb0 = *(const uint4*)(B + (size_t)(k0 + br) * KVW + bc);
            rb1 = *(const uint4*)(B + (size_t)(k0 + br) * KVW + bc + 8);
        }
#pragma unroll
        for (int ks = 0; ks < BK; ks += 16) {
            AFragH af[4];
            BFragHR bf[2];
#pragma unroll
            for (int i = 0; i < 4; i++)
                wmma::load_matrix_sync(af[i], sA[cur] + (wm * 64 + i * 16) * HPITCH + ks, HPITCH);
#pragma unroll
            for (int jj = 0; jj < 2; jj++)
                wmma::load_matrix_sync(bf[jj], sB[cur] + ks * HPITCH_B + (wn * 32 + jj * 16), HPITCH_B);
#pragma unroll
            for (int i = 0; i < 4; i++)
#pragma unroll
                for (int jj = 0; jj < 2; jj++)
                    wmma::mma_sync(c[i][jj], af[i], bf[jj], c[i][jj]);
        }
        if (t + 1 < nt) {
            const int nxt = cur ^ 1;
            __half* a = sA[nxt] + row * HPITCH + c0;
            *(uint4*)a = ra0; *(uint4*)(a + 8) = ra1;
            __half* bb = sB[nxt] + br * HPITCH_B + bc;
            *(uint4*)bb = rb0; *(uint4*)(bb + 8) = rb1;
        }
        __syncthreads();
    }

    float* stage = reinterpret_cast<float*>(smem) + wid * 256;
    const int r  = lane >> 1;
    const int cq = (lane & 1) << 3;
#pragma unroll
    for (int i = 0; i < 4; i++) {
#pragma unroll
        for (int jj = 0; jj < 2; jj++) {
            wmma::store_matrix_sync(stage, c[i][jj], 16, wmma::mem_row_major);
            __syncwarp();
            const size_t row_g = (size_t)(m0 + wm * 64 + i * 16 + r);
            const size_t col_g = (size_t)(wn * 32 + jj * 16 + cq);
            float4 v0 = *(float4*)&stage[r * 16 + cq];
            float4 v1 = *(float4*)&stage[r * 16 + cq + 4];
            __half2 hh[4];
            hh[0] = __floats2half2_rn(v0.x, v0.y);
            hh[1] = __floats2half2_rn(v0.z, v0.w);
            hh[2] = __floats2half2_rn(v1.x, v1.y);
            hh[3] = __floats2half2_rn(v1.z, v1.w);
            *(uint4*)&C[row_g * HIDN + col_g] = *(uint4*)hh;
            __syncwarp();
        }
    }
}

// ---------------- elementwise / reduction kernels ----------------

__global__ void __launch_bounds__(256)
f2h_kernel(const float* __restrict__ in, __half* __restrict__ out, int n)
{
    int i = (blockIdx.x * blockDim.x + threadIdx.x) * 4;
    int stride = gridDim.x * blockDim.x * 4;
    for (; i < n; i += stride) {
        float4 v = *(const float4*)(in + i);
        ((__half2*)(out + i))[0] = __floats2half2_rn(v.x, v.y);
        ((__half2*)(out + i))[1] = __floats2half2_rn(v.z, v.w);
    }
}

__global__ void __launch_bounds__(256)
bias_concat_kernel(const float* __restrict__ bq, const float* __restrict__ bk,
                   const float* __restrict__ bv, float* __restrict__ dst)
{
    int i = blockIdx.x * blockDim.x + threadIdx.x;
    if (i < HIDN) dst[i] = bq[i];
    else if (i < HIDN + KVW) dst[i] = bk[i - HIDN];
    else if (i < NQKV) dst[i] = bv[i - HIDN - KVW];
}

__global__ void __launch_bounds__(256)
v_extract_kernel(const float* __restrict__ qkv, __half* __restrict__ v16)
{
    int idx = (blockIdx.x * blockDim.x + threadIdx.x) * 4;
    if (idx >= T_TOK * KVW) return;
    int t = idx >> 9;
    int j = idx & 511;
    float4 v = *(const float4*)(qkv + (size_t)t * NQKV + HIDN + KVW + j);
    ((__half2*)(v16 + idx))[0] = __floats2half2_rn(v.x, v.y);
    ((__half2*)(v16 + idx))[1] = __floats2half2_rn(v.z, v.w);
}

__global__ void __launch_bounds__(256)
softmax_kernel(const float* __restrict__ s, __half* __restrict__ p16)
{
    const size_t base = (size_t)blockIdx.x * SEQ;
    const int r = blockIdx.x & (SEQ - 1);
    const int L = ((r >> 7) + 1) << 7;
    const int tid = threadIdx.x;
    __shared__ float red[8];

    float vals[4];
    float mx = -1e30f;
    int cnt = 0;
    for (int idx = tid; idx < L; idx += 256) {
        vals[cnt] = s[base + idx];
        mx = fmaxf(mx, vals[cnt]);
        cnt++;
    }
#pragma unroll
    for (int o = 16; o > 0; o >>= 1) mx = fmaxf(mx, __shfl_xor_sync(0xffffffffu, mx, o));
    if ((tid & 31) == 0) red[tid >> 5] = mx;
    __syncthreads();
    float m2 = fmaxf(fmaxf(fmaxf(red[0], red[1]), fmaxf(red[2], red[3])),
                     fmaxf(fmaxf(red[4], red[5]), fmaxf(red[6], red[7])));
    __syncthreads();

    float sum = 0.f;
    for (int c = 0; c < cnt; c++) {
        vals[c] = expf(vals[c] - m2);
        sum += vals[c];
    }
#pragma unroll
    for (int o = 16; o > 0; o >>= 1) sum += __shfl_xor_sync(0xffffffffu, sum, o);
    if ((tid & 31) == 0) red[tid >> 5] = sum;
    __syncthreads();
    float tot = red[0] + red[1] + red[2] + red[3] + red[4] + red[5] + red[6] + red[7];
    float inv = 1.f / tot;
    int c = 0;
    for (int idx = tid; idx < L; idx += 256, c++)
        p16[base + idx] = __float2half_rn(vals[c] * inv);
}

__global__ void __launch_bounds__(256)
rmsnorm_h_kernel(const float* __restrict__ x, const float* __restrict__ w,
                 __half* __restrict__ out)
{
    const size_t base = (size_t)blockIdx.x * HIDN;
    const int tid = threadIdx.x;
    __shared__ float red[8];

    float v[8];
    float ss = 0.f;
#pragma unroll
    for (int jj = 0; jj < 8; jj++) {
        v[jj] = x[base + tid + jj * 256];
        ss += v[jj] * v[jj];
    }
#pragma unroll
    for (int o = 16; o > 0; o >>= 1) ss += __shfl_xor_sync(0xffffffffu, ss, o);
    if ((tid & 31) == 0) red[tid >> 5] = ss;
    __syncthreads();
    float tot = red[0] + red[1] + red[2] + red[3] + red[4] + red[5] + red[6] + red[7];
    float r = rsqrtf(tot * (1.f / HIDN) + EPSV);
#pragma unroll
    for (int jj = 0; jj < 8; jj++)
        out[base + tid + jj * 256] = __float2half_rn(v[jj] * r * w[tid + jj * 256]);
}

__global__ void __launch_bounds__(128)
head_rms_rope_kernel(const float* __restrict__ buf, int instride, int inoff,
                     const float* __restrict__ w,
                     const float* __restrict__ cs, const float* __restrict__ sn,
                     __half* __restrict__ out16, int outstride)
{
    const int t = blockIdx.x;
    const int h = blockIdx.y;
    const int i = threadIdx.x;
    const size_t iidx = (size_t)t * instride + inoff + h * HD + i;
    const size_t oidx = (size_t)t * outstride + h * HD + i;

    float v = buf[iidx];
    float ss = v * v;
#pragma unroll
    for (int o = 16; o > 0; o >>= 1) ss += __shfl_xor_sync(0xffffffffu, ss, o);
    __shared__ float red[4];
    if ((i & 31) == 0) red[i >> 5] = ss;
    __syncthreads();
    float tot = red[0] + red[1] + red[2] + red[3];
    float n = v * rsqrtf(tot * (1.f / HD) + EPSV) * w[i];

    __shared__ float sm[HD];
    sm[i] = n;
    __syncthreads();
    float rot = (i < 64) ? -sm[i + 64] : sm[i - 64];
    out16[oidx] = __float2half_rn(n * cs[(size_t)t * HD + i] + rot * sn[(size_t)t * HD + i]);
}

extern "C" void kernel_launch(void* const* d_in, const int* in_sizes, int n_in,
                              void* d_out, int out_size)
{
    const float* x    = (const float*)d_in[0];
    const float* cosv = (const float*)d_in[1];
    const float* sinv = (const float*)d_in[2];
    const float* wq   = (const float*)d_in[4];
    const float* bq   = (const float*)d_in[5];
    const float* wk   = (const float*)d_in[6];
    const float* bk   = (const float*)d_in[7];
    const float* wv   = (const float*)d_in[8];
    const float* bv   = (const float*)d_in[9];
    const float* wo   = (const float*)d_in[10];
    const float* qw   = (const float*)d_in[11];
    const float* kw   = (const float*)d_in[12];
    const float* ln1  = (const float*)d_in[13];
    const float* ln2  = (const float*)d_in[14];
    const float* wg   = (const float*)d_in[15];
    const float* wu   = (const float*)d_in[16];
    const float* wd   = (const float*)d_in[17];
    float* out = (float*)d_out;

    float* s = nullptr;
    cudaGetSymbolAddress((void**)&s, g_scratch);
    __half* hs = nullptr;
    cudaGetSymbolAddress((void**)&hs, g_hscratch);

    float* qkv    = s + OFF_QKV;
    float* scores = s + OFF_SCORES;
    float* x2     = s + OFF_X2;
    float* biasc  = s + OFF_BIAS;

    __half* hwqkv = hs + HW_QKV;
    __half* hwo   = hs + HW_O;
    __half* hwg   = hs + HW_G;
    __half* hwu   = hs + HW_U;
    __half* hwd   = hs + HW_D;
    __half* h16   = hs + H_H16;
    __half* q16   = hs + H_Q16;
    __half* k16   = hs + H_K16;
    __half* v16   = hs + H_V16;
    __half* p16   = hs + H_P16;
    __half* at16  = hs + H_ATTN16;
    __half* g16   = hs + H_G16;

    cudaFuncSetAttribute(casgemm_tn<1, 0>, cudaFuncAttributeMaxDynamicSharedMemorySize, CAS_SMEM_BYTES);
    cudaFuncSetAttribute(casgemm_tn<2, 0>, cudaFuncAttributeMaxDynamicSharedMemorySize, CAS_SMEM_BYTES);
    cudaFuncSetAttribute(casgemm_tn<0, 1>, cudaFuncAttributeMaxDynamicSharedMemorySize, CAS_SMEM_BYTES);
    cudaFuncSetAttribute(casgemm_tn<3, 1>, cudaFuncAttributeMaxDynamicSharedMemorySize, CAS_SMEM_BYTES);

    // 0. weights fp32 -> fp16 (QKV concatenated)
    f2h_kernel<<<2048, 256>>>(wq, hwqkv,                       HIDN * HIDN);
    f2h_kernel<<<1024, 256>>>(wk, hwqkv + HIDN * HIDN,         KVW * HIDN);
    f2h_kernel<<<1024, 256>>>(wv, hwqkv + (HIDN + KVW) * HIDN, KVW * HIDN);
    f2h_kernel<<<2048, 256>>>(wo, hwo, HIDN * HIDN);
    f2h_kernel<<<4096, 256>>>(wg, hwg, FF * HIDN);
    f2h_kernel<<<4096, 256>>>(wu, hwu, FF * HIDN);
    f2h_kernel<<<4096, 256>>>(wd, hwd, HIDN * FF);
    bias_concat_kernel<<<12, 256>>>(bq, bk, bv, biasc);

    // 1. h16 = rmsnorm(x, ln1)
    rmsnorm_h_kernel<<<T_TOK, 256>>>(x, ln1, h16);

    // 2. fused QKV projection (+bias)
    casgemm_tn<1, 0><<<dim3(NQKV / 128, T_TOK / 128), 256, CAS_SMEM_BYTES>>>(
        h16, HIDN, hwqkv, HIDN, qkv, NQKV, HIDN, biasc, nullptr, nullptr);

    // 3-5. per-head RMS + RoPE -> q16/k16 ; extract v16
    head_rms_rope_kernel<<<dim3(T_TOK, NH),  HD>>>(qkv, NQKV, 0,    qw, cosv, sinv, q16, HIDN);
    head_rms_rope_kernel<<<dim3(T_TOK, NKV), HD>>>(qkv, NQKV, HIDN, kw, cosv, sinv, k16, KVW);
    v_extract_kernel<<<(T_TOK * KVW / 4 + 255) / 256, 256>>>(qkv, v16);

    // 6. scores (lower triangle, analytic mask)
    hscores<<<dim3(SEQ / BN, SEQ / BM, BATCH * NH), 256>>>(q16, k16, scores);

    // 7. softmax -> p16
    softmax_kernel<<<BATCH * NH * SEQ, 256>>>(scores, p16);

    // 8. attn16 = P @ V (causal-trimmed)
    hpv<<<dim3(1, SEQ / BM, BATCH * NH), 256>>>(p16, v16, at16);

    // 9. x2 = x + attn @ wo^T
    casgemm_tn<2, 0><<<dim3(HIDN / 128, T_TOK / 128), 256, CAS_SMEM_BYTES>>>(
        at16, HIDN, hwo, HIDN, x2, HIDN, HIDN, nullptr, x, nullptr);

    // 10. h16 = rmsnorm(x2, ln2)
    rmsnorm_h_kernel<<<T_TOK, 256>>>(x2, ln2, h16);

    // 11. gate -> g16 (fp16)
    casgemm_tn<0, 1><<<dim3(FF / 128, T_TOK / 128), 256, CAS_SMEM_BYTES>>>(
        h16, HIDN, hwg, HIDN, g16, FF, HIDN, nullptr, nullptr, nullptr);

    // 12. up + fused silu: g16 = silu(g16) * up  (in place)
    casgemm_tn<3, 1><<<dim3(FF / 128, T_TOK / 128), 256, CAS_SMEM_BYTES>>>(
        h16, HIDN, hwu, HIDN, g16, FF, HIDN, nullptr, nullptr, g16);

    // 13. out = x2 + g16 @ wd^T
    casgemm_tn<2, 0><<<dim3(HIDN / 128, T_TOK / 128), 256, CAS_SMEM_BYTES>>>(
        g16, FF, hwd, FF, out, HIDN, FF, nullptr, x2, nullptr);
}

// round 10
// speedup vs baseline: 1.5252x; 1.0161x over previous
#include <cuda_runtime.h>
#include <cuda_fp16.h>
#include <mma.h>
#include <math.h>
#include <stdint.h>

using namespace nvcuda;

// ---------------- problem constants ----------------
#define T_TOK 4096
#define HIDN  2048
#define NH    16
#define NKV   4
#define HD    128
#define FF    8192
#define BATCH 4
#define SEQ   1024
#define GRP   (NH / NKV)
#define KVW   (NKV * HD)          // 512
#define NQKV  (HIDN + 2 * KVW)    // 3072
#define EPSV  1e-6f
#define SCALE 0.08838834764831845f
#define NEGV  -1000000000.0f

// ---------------- fp32 scratch ----------------
#define OFF_SCORES ((size_t)0)           // 64*1024*1024
#define OFF_X2     ((size_t)67108864)    // 4096*2048
#define OFF_BIAS   ((size_t)75497472)    // 3072 (pad)
#define SCRATCH_FLOATS ((size_t)75501568)
__device__ float g_scratch[SCRATCH_FLOATS];

// ---------------- fp16 scratch ----------------
#define HW_QKV   ((size_t)0)             // 3072*2048
#define HW_O     ((size_t)6291456)       // 2048*2048
#define HW_G     ((size_t)10485760)      // 8192*2048
#define HW_U     ((size_t)27262976)
#define HW_D     ((size_t)44040192)
#define H_H16    ((size_t)60817408)      // 4096*2048
#define H_QKV16  ((size_t)69206016)      // 4096*3072
#define H_Q16    ((size_t)81788928)      // 4096*2048
#define H_K16    ((size_t)90177536)      // 4096*512
#define H_P16    ((size_t)92274688)      // 64*1024*1024
#define H_ATTN16 ((size_t)159383552)     // 4096*2048
#define H_G16    ((size_t)167772160)     // 4096*8192
#define HSCRATCH_HALVES ((size_t)201326592)
__device__ __half g_hscratch[HSCRATCH_HALVES];

// ---------------- cp.async helpers ----------------
__device__ __forceinline__ void cp16(uint32_t dst, const void* src) {
    asm volatile("cp.async.cg.shared.global [%0], [%1], 16;" :: "r"(dst), "l"(src));
}
__device__ __forceinline__ void cp_commit() {
    asm volatile("cp.async.commit_group;");
}
template <int N>
__device__ __forceinline__ void cp_wait() {
    asm volatile("cp.async.wait_group %0;" :: "n"(N));
}

typedef wmma::fragment<wmma::matrix_a, 16, 16, 16, __half, wmma::row_major> AFragH;
typedef wmma::fragment<wmma::matrix_b, 16, 16, 16, __half, wmma::col_major> BFragHC;
typedef wmma::fragment<wmma::matrix_b, 16, 16, 16, __half, wmma::row_major> BFragHR;
typedef wmma::fragment<wmma::accumulator, 16, 16, 16, float> CFragH;

// ============================================================
// cp.async weight GEMM (R9-proven): 256 thr, 8 warps, BK=64,
// 3 stages, 2 CTAs/SM.  C[M,N] = A[M,K] @ B[N,K]^T.
// EPI: 0 none, 1 +bias, 2 +res(fp32), 3 silu(resH)*acc.
// HOUT: 0 fp32 C, 1 fp16 C.
// ============================================================
#define BKC 64
#define CPITCH 72
#define CSTAGE (128 * CPITCH)
#define CAS_SMEM_BYTES (3 * 2 * CSTAGE * 2)   // 110592 B

template <int EPI, int HOUT>
__global__ void __launch_bounds__(256, 2)
casgemm_tn(const __half* __restrict__ A, int lda,
           const __half* __restrict__ B, int ldb,
           void* __restrict__ Cv, int ldc, int K,
           const float* __restrict__ bias,
           const float* __restrict__ res,
           const __half* __restrict__ resH)
{
    extern __shared__ __half csmem[];
    const uint32_t sm32 = (uint32_t)__cvta_generic_to_shared(csmem);

    const int tid  = threadIdx.x;
    const int wid  = tid >> 5;
    const int lane = tid & 31;
    const int m0 = blockIdx.y * 128;
    const int n0 = blockIdx.x * 128;
    const int wm = wid & 1, wn = wid >> 1;

    CFragH c[4][2];
#pragma unroll
    for (int i = 0; i < 4; i++)
#pragma unroll
        for (int j = 0; j < 2; j++) wmma::fill_fragment(c[i][j], 0.f);

    const int row = tid >> 1;
    const int cb  = (tid & 1) << 5;
    const __half* gA = A + (size_t)(m0 + row) * lda + cb;
    const __half* gB = B + (size_t)(n0 + row) * ldb + cb;
    const uint32_t tA = sm32 + (uint32_t)(row * CPITCH + cb) * 2u;
    const uint32_t tB = tA + (uint32_t)CSTAGE * 2u;

#define CAS_LOAD(slot, k0) do {                                         \
        const uint32_t _o = (uint32_t)(slot) * (2u * CSTAGE * 2u);      \
        _Pragma("unroll")                                               \
        for (int _u = 0; _u < 4; _u++) {                                \
            cp16(tA + _o + _u * 16u, gA + (k0) + _u * 8);               \
            cp16(tB + _o + _u * 16u, gB + (k0) + _u * 8);               \
        }                                                               \
    } while (0)

    const int nt = K / BKC;

    CAS_LOAD(0, 0);      cp_commit();
    CAS_LOAD(1, BKC);    cp_commit();

    for (int t = 0; t < nt; t++) {
        cp_wait<1>();
        __syncthreads();
        if (t + 2 < nt) CAS_LOAD((t + 2) % 3, (t + 2) * BKC);
        cp_commit();

        const __half* sA = csmem + (t % 3) * 2 * CSTAGE;
        const __half* sB = sA + CSTAGE;
#pragma unroll
        for (int ks = 0; ks < BKC; ks += 16) {
            AFragH af[4];
            BFragHC bf[2];
#pragma unroll
            for (int i = 0; i < 4; i++)
                wmma::load_matrix_sync(af[i], sA + (wm * 64 + i * 16) * CPITCH + ks, CPITCH);
#pragma unroll
            for (int j = 0; j < 2; j++)
                wmma::load_matrix_sync(bf[j], sB + (wn * 32 + j * 16) * CPITCH + ks, CPITCH);
#pragma unroll
            for (int i = 0; i < 4; i++)
#pragma unroll
                for (int j = 0; j < 2; j++)
                    wmma::mma_sync(c[i][j], af[i], bf[j], c[i][j]);
        }
    }
    __syncthreads();

    float* stage = reinterpret_cast<float*>(csmem) + wid * 256;
    const int r  = lane >> 1;
    const int cq = (lane & 1) << 3;
#pragma unroll
    for (int i = 0; i < 4; i++) {
#pragma unroll
        for (int j = 0; j < 2; j++) {
            wmma::store_matrix_sync(stage, c[i][j], 16, wmma::mem_row_major);
            __syncwarp();
            const size_t row_g = (size_t)(m0 + wm * 64 + i * 16 + r);
            const size_t col_g = (size_t)(n0 + wn * 32 + j * 16 + cq);
            float4 v0 = *(float4*)&stage[r * 16 + cq];
            float4 v1 = *(float4*)&stage[r * 16 + cq + 4];
            if (EPI == 1) {
                float4 b0 = *(const float4*)&bias[col_g];
                float4 b1 = *(const float4*)&bias[col_g + 4];
                v0.x += b0.x; v0.y += b0.y; v0.z += b0.z; v0.w += b0.w;
                v1.x += b1.x; v1.y += b1.y; v1.z += b1.z; v1.w += b1.w;
            }
            if (EPI == 2) {
                float4 r0 = *(const float4*)&res[row_g * ldc + col_g];
                float4 r1 = *(const float4*)&res[row_g * ldc + col_g + 4];
                v0.x += r0.x; v0.y += r0.y; v0.z += r0.z; v0.w += r0.w;
                v1.x += r1.x; v1.y += r1.y; v1.z += r1.z; v1.w += r1.w;
            }
            if (EPI == 3) {
                uint4 gu = *(const uint4*)&resH[row_g * ldc + col_g];
                __half2* gh = (__half2*)&gu;
                float2 g0 = __half22float2(gh[0]);
                float2 g1 = __half22float2(gh[1]);
                float2 g2 = __half22float2(gh[2]);
                float2 g3 = __half22float2(gh[3]);
                v0.x *= g0.x / (1.f + expf(-g0.x));
                v0.y *= g0.y / (1.f + expf(-g0.y));
                v0.z *= g1.x / (1.f + expf(-g1.x));
                v0.w *= g1.y / (1.f + expf(-g1.y));
                v1.x *= g2.x / (1.f + expf(-g2.x));
                v1.y *= g2.y / (1.f + expf(-g2.y));
                v1.z *= g3.x / (1.f + expf(-g3.x));
                v1.w *= g3.y / (1.f + expf(-g3.y));
            }
            if (HOUT) {
                __half* C = (__half*)Cv;
                __half2 h[4];
                h[0] = __floats2half2_rn(v0.x, v0.y);
                h[1] = __floats2half2_rn(v0.z, v0.w);
                h[2] = __floats2half2_rn(v1.x, v1.y);
                h[3] = __floats2half2_rn(v1.z, v1.w);
                *(uint4*)&C[row_g * ldc + col_g] = *(uint4*)h;
            } else {
                float* C = (float*)Cv;
                *(float4*)&C[row_g * ldc + col_g] = v0;
                *(float4*)&C[row_g * ldc + col_g + 4] = v1;
            }
            __syncwarp();
        }
    }
#undef CAS_LOAD
}

// ============================================================
// PV with cp.async core: attn16 = P16 @ V16 (NN, causal-trimmed)
// A = p16 [SEQ, SEQ], B = V strided (ldv), C = at16 [*, HIDN]
// ============================================================
#define PV_APITCH 72
#define PV_ASTAGE (128 * PV_APITCH)     // 9216 halves
#define PV_BPITCH 136
#define PV_BSTAGE (64 * PV_BPITCH)      // 8704 halves
#define PV_SLOT   (PV_ASTAGE + PV_BSTAGE)
#define PV_SMEM_BYTES (3 * PV_SLOT * 2) // 107520 B

__global__ void __launch_bounds__(256, 2)
hpv_cas(const __half* __restrict__ p, const __half* __restrict__ v, int ldv,
        __half* __restrict__ out)
{
    extern __shared__ __half csmem[];
    const uint32_t sm32 = (uint32_t)__cvta_generic_to_shared(csmem);

    const int z = blockIdx.z;
    const int b = z / NH, h = z % NH, kvh = h / GRP;
    const int m0 = blockIdx.y * 128;
    const __half* A = p + (size_t)z * SEQ * SEQ;
    const __half* B = v + (size_t)b * SEQ * ldv + (size_t)kvh * HD;
    __half* C = out + (size_t)b * SEQ * HIDN + (size_t)h * HD;

    const int tid  = threadIdx.x;
    const int wid  = tid >> 5;
    const int lane = tid & 31;
    const int wm = wid & 1, wn = wid >> 1;

    CFragH c[4][2];
#pragma unroll
    for (int i = 0; i < 4; i++)
#pragma unroll
        for (int j = 0; j < 2; j++) wmma::fill_fragment(c[i][j], 0.f);

    const int arow = tid >> 1;           // 0..127
    const int acb  = (tid & 1) << 5;     // 0 or 32
    const int brow = tid >> 2;           // 0..63
    const int bcb  = (tid & 3) << 5;     // 0,32,64,96
    const __half* gA = A + (size_t)(m0 + arow) * SEQ + acb;
    const uint32_t tA = sm32 + (uint32_t)(arow * PV_APITCH + acb) * 2u;
    const uint32_t tB = sm32 + (uint32_t)(PV_ASTAGE + brow * PV_BPITCH + bcb) * 2u;

#define PV_LOAD(slot, k0) do {                                          \
        const uint32_t _o = (uint32_t)(slot) * (PV_SLOT * 2u);          \
        const __half* _gb = B + (size_t)((k0) + brow) * ldv + bcb;      \
        _Pragma("unroll")                                               \
        for (int _u = 0; _u < 4; _u++) {                                \
            cp16(tA + _o + _u * 16u, gA + (k0) + _u * 8);               \
            cp16(tB + _o + _u * 16u, _gb + _u * 8);                     \
        }                                                               \
    } while (0)

    const int nt = (m0 + 128) / BKC;     // causal length / 64, >= 2

    PV_LOAD(0, 0);    cp_commit();
    PV_LOAD(1, BKC);  cp_commit();

    for (int t = 0; t < nt; t++) {
        cp_wait<1>();
        __syncthreads();
        if (t + 2 < nt) PV_LOAD((t + 2) % 3, (t + 2) * BKC);
        cp_commit();

        const __half* sA = csmem + (t % 3) * PV_SLOT;
        const __half* sB = sA + PV_ASTAGE;
#pragma unroll
        for (int ks = 0; ks < BKC; ks += 16) {
            AFragH af[4];
            BFragHR bf[2];
#pragma unroll
            for (int i = 0; i < 4; i++)
                wmma::load_matrix_sync(af[i], sA + (wm * 64 + i * 16) * PV_APITCH + ks, PV_APITCH);
#pragma unroll
            for (int j = 0; j < 2; j++)
                wmma::load_matrix_sync(bf[j], sB + ks * PV_BPITCH + (wn * 32 + j * 16), PV_BPITCH);
#pragma unroll
            for (int i = 0; i < 4; i++)
#pragma unroll
                for (int j = 0; j < 2; j++)
                    wmma::mma_sync(c[i][j], af[i], bf[j], c[i][j]);
        }
    }
    __syncthreads();

    float* stage = reinterpret_cast<float*>(csmem) + wid * 256;
    const int r  = lane >> 1;
    const int cq = (lane & 1) << 3;
#pragma unroll
    for (int i = 0; i < 4; i++) {
#pragma unroll
        for (int j = 0; j < 2; j++) {
            wmma::store_matrix_sync(stage, c[i][j], 16, wmma::mem_row_major);
            __syncwarp();
            const size_t row_g = (size_t)(m0 + wm * 64 + i * 16 + r);
            const size_t col_g = (size_t)(wn * 32 + j * 16 + cq);
            float4 v0 = *(float4*)&stage[r * 16 + cq];
            float4 v1 = *(float4*)&stage[r * 16 + cq + 4];
            __half2 hh[4];
            hh[0] = __floats2half2_rn(v0.x, v0.y);
            hh[1] = __floats2half2_rn(v0.z, v0.w);
            hh[2] = __floats2half2_rn(v1.x, v1.y);
            hh[3] = __floats2half2_rn(v1.z, v1.w);
            *(uint4*)&C[row_g * HIDN + col_g] = *(uint4*)hh;
            __syncwarp();
        }
    }
#undef PV_LOAD
}

// ============================================================
// Scores: q16(prescaled).k16 + analytic causal mask -> fp32
// (R8-proven core)
// ============================================================
#define BM 128
#define BN 128
#define BK 32
#define HPITCH 40
#define HSTAGE (128 * HPITCH)

__global__ void __launch_bounds__(256, 2)
hscores(const __half* __restrict__ q, const __half* __restrict__ k,
        float* __restrict__ scores)
{
    if (blockIdx.x > blockIdx.y) return;

    const int z = blockIdx.z;
    const int b = z / NH, h = z % NH, kvh = h / GRP;
    const int m0 = blockIdx.y * BM;
    const int n0 = blockIdx.x * BN;
    const __half* A = q + (size_t)b * SEQ * HIDN + (size_t)h * HD;
    const __half* B = k + (size_t)b * SEQ * KVW + (size_t)kvh * HD;
    float* C = scores + (size_t)z * SEQ * SEQ;
    const bool diag = (blockIdx.x == blockIdx.y);

    __shared__ __align__(16) __half smem[4 * HSTAGE];
    __half* sA[2] = { smem,              smem + HSTAGE };
    __half* sB[2] = { smem + 2 * HSTAGE, smem + 3 * HSTAGE };

    const int tid  = threadIdx.x;
    const int wid  = tid >> 5;
    const int lane = tid & 31;
    const int wm = wid & 1, wn = wid >> 1;

    CFragH c[4][2];
#pragma unroll
    for (int i = 0; i < 4; i++)
#pragma unroll
        for (int jj = 0; jj < 2; jj++) wmma::fill_fragment(c[i][jj], 0.f);

    const int row = tid >> 1;
    const int c0  = (tid & 1) << 4;
    const __half* gA = A + (size_t)(m0 + row) * HIDN + c0;
    const __half* gB = B + (size_t)(n0 + row) * KVW + c0;

    uint4 ra0, ra1, rb0, rb1;
    ra0 = *(const uint4*)(gA);
    ra1 = *(const uint4*)(gA + 8);
    rb0 = *(const uint4*)(gB);
    rb1 = *(const uint4*)(gB + 8);
    {
        __half* a = sA[0] + row * HPITCH + c0;
        *(uint4*)a = ra0; *(uint4*)(a + 8) = ra1;
        __half* bb = sB[0] + row * HPITCH + c0;
        *(uint4*)bb = rb0; *(uint4*)(bb + 8) = rb1;
    }
    __syncthreads();

    const int nt = HD / BK;
    for (int t = 0; t < nt; t++) {
        const int cur = t & 1;
        if (t + 1 < nt) {
            const int k0 = (t + 1) * BK;
            ra0 = *(const uint4*)(gA + k0);
            ra1 = *(const uint4*)(gA + k0 + 8);
            rb0 = *(const uint4*)(gB + k0);
            rb1 = *(const uint4*)(gB + k0 + 8);
        }
#pragma unroll
        for (int ks = 0; ks < BK; ks += 16) {
            AFragH af[4];
            BFragHC bf[2];
#pragma unroll
            for (int i = 0; i < 4; i++)
                wmma::load_matrix_sync(af[i], sA[cur] + (wm * 64 + i * 16) * HPITCH + ks, HPITCH);
#pragma unroll
            for (int jj = 0; jj < 2; jj++)
                wmma::load_matrix_sync(bf[jj], sB[cur] + (wn * 32 + jj * 16) * HPITCH + ks, HPITCH);
#pragma unroll
            for (int i = 0; i < 4; i++)
#pragma unroll
                for (int jj = 0; jj < 2; jj++)
                    wmma::mma_sync(c[i][jj], af[i], bf[jj], c[i][jj]);
        }
        if (t + 1 < nt) {
            const int nxt = cur ^ 1;
            __half* a = sA[nxt] + row * HPITCH + c0;
            *(uint4*)a = ra0; *(uint4*)(a + 8) = ra1;
            __half* bb = sB[nxt] + row * HPITCH + c0;
            *(uint4*)bb = rb0; *(uint4*)(bb + 8) = rb1;
        }
        __syncthreads();
    }

    float* stage = reinterpret_cast<float*>(smem) + wid * 256;
    const int r  = lane >> 1;
    const int cq = (lane & 1) << 3;
#pragma unroll
    for (int i = 0; i < 4; i++) {
#pragma unroll
        for (int jj = 0; jj < 2; jj++) {
            wmma::store_matrix_sync(stage, c[i][jj], 16, wmma::mem_row_major);
            __syncwarp();
            const size_t row_g = (size_t)(m0 + wm * 64 + i * 16 + r);
            const size_t col_g = (size_t)(n0 + wn * 32 + jj * 16 + cq);
            float4 v0 = *(float4*)&stage[r * 16 + cq];
            float4 v1 = *(float4*)&stage[r * 16 + cq + 4];
            if (diag) {
                if (col_g + 0 > row_g) v0.x += NEGV;
                if (col_g + 1 > row_g) v0.y += NEGV;
                if (col_g + 2 > row_g) v0.z += NEGV;
                if (col_g + 3 > row_g) v0.w += NEGV;
                if (col_g + 4 > row_g) v1.x += NEGV;
                if (col_g + 5 > row_g) v1.y += NEGV;
                if (col_g + 6 > row_g) v1.z += NEGV;
                if (col_g + 7 > row_g) v1.w += NEGV;
            }
            *(float4*)&C[row_g * SEQ + col_g] = v0;
            *(float4*)&C[row_g * SEQ + col_g + 4] = v1;
            __syncwarp();
        }
    }
}

// ---------------- elementwise / reduction kernels ----------------

__global__ void __launch_bounds__(256)
f2h_kernel(const float* __restrict__ in, __half* __restrict__ out, int n)
{
    int i = (blockIdx.x * blockDim.x + threadIdx.x) * 4;
    int stride = gridDim.x * blockDim.x * 4;
    for (; i < n; i += stride) {
        float4 v = *(const float4*)(in + i);
        ((__half2*)(out + i))[0] = __floats2half2_rn(v.x, v.y);
        ((__half2*)(out + i))[1] = __floats2half2_rn(v.z, v.w);
    }
}

__global__ void __launch_bounds__(256)
bias_concat_kernel(const float* __restrict__ bq, const float* __restrict__ bk,
                   const float* __restrict__ bv, float* __restrict__ dst)
{
    int i = blockIdx.x * blockDim.x + threadIdx.x;
    if (i < HIDN) dst[i] = bq[i];
    else if (i < HIDN + KVW) dst[i] = bk[i - HIDN];
    else if (i < NQKV) dst[i] = bv[i - HIDN - KVW];
}

__global__ void __launch_bounds__(256)
softmax_kernel(const float* __restrict__ s, __half* __restrict__ p16)
{
    const size_t base = (size_t)blockIdx.x * SEQ;
    const int r = blockIdx.x & (SEQ - 1);
    const int L = ((r >> 7) + 1) << 7;
    const int tid = threadIdx.x;
    __shared__ float red[8];

    float vals[4];
    float mx = -1e30f;
    int cnt = 0;
    for (int idx = tid; idx < L; idx += 256) {
        vals[cnt] = s[base + idx];
        mx = fmaxf(mx, vals[cnt]);
        cnt++;
    }
#pragma unroll
    for (int o = 16; o > 0; o >>= 1) mx = fmaxf(mx, __shfl_xor_sync(0xffffffffu, mx, o));
    if ((tid & 31) == 0) red[tid >> 5] = mx;
    __syncthreads();
    float m2 = fmaxf(fmaxf(fmaxf(red[0], red[1]), fmaxf(red[2], red[3])),
                     fmaxf(fmaxf(red[4], red[5]), fmaxf(red[6], red[7])));
    __syncthreads();

    float sum = 0.f;
    for (int c = 0; c < cnt; c++) {
        vals[c] = expf(vals[c] - m2);
        sum += vals[c];
    }
#pragma unroll
    for (int o = 16; o > 0; o >>= 1) sum += __shfl_xor_sync(0xffffffffu, sum, o);
    if ((tid & 31) == 0) red[tid >> 5] = sum;
    __syncthreads();
    float tot = red[0] + red[1] + red[2] + red[3] + red[4] + red[5] + red[6] + red[7];
    float inv = 1.f / tot;
    int c = 0;
    for (int idx = tid; idx < L; idx += 256, c++)
        p16[base + idx] = __float2half_rn(vals[c] * inv);
}

__global__ void __launch_bounds__(256)
rmsnorm_h_kernel(const float* __restrict__ x, const float* __restrict__ w,
                 __half* __restrict__ out)
{
    const size_t base = (size_t)blockIdx.x * HIDN;
    const int tid = threadIdx.x;
    __shared__ float red[8];

    float v[8];
    float ss = 0.f;
#pragma unroll
    for (int jj = 0; jj < 8; jj++) {
        v[jj] = x[base + tid + jj * 256];
        ss += v[jj] * v[jj];
    }
#pragma unroll
    for (int o = 16; o > 0; o >>= 1) ss += __shfl_xor_sync(0xffffffffu, ss, o);
    if ((tid & 31) == 0) red[tid >> 5] = ss;
    __syncthreads();
    float tot = red[0] + red[1] + red[2] + red[3] + red[4] + red[5] + red[6] + red[7];
    float r = rsqrtf(tot * (1.f / HIDN) + EPSV);
#pragma unroll
    for (int jj = 0; jj < 8; jj++)
        out[base + tid + jj * 256] = __float2half_rn(v[jj] * r * w[tid + jj * 256]);
}

// per-head RMS + RoPE: fp16 in (stride instride, offset inoff), fp16 out * outscale
__global__ void __launch_bounds__(128)
head_rms_rope_h_kernel(const __half* __restrict__ buf, int instride, int inoff,
                       const float* __restrict__ w,
                       const float* __restrict__ cs, const float* __restrict__ sn,
                       __half* __restrict__ out16, int outstride, float outscale)
{
    const int t = blockIdx.x;
    const int h = blockIdx.y;
    const int i = threadIdx.x;
    const size_t iidx = (size_t)t * instride + inoff + h * HD + i;
    const size_t oidx = (size_t)t * outstride + h * HD + i;

    float v = __half2float(buf[iidx]);
    float ss = v * v;
#pragma unroll
    for (int o = 16; o > 0; o >>= 1) ss += __shfl_xor_sync(0xffffffffu, ss, o);
    __shared__ float red[4];
    if ((i & 31) == 0) red[i >> 5] = ss;
    __syncthreads();
    float tot = red[0] + red[1] + red[2] + red[3];
    float n = v * rsqrtf(tot * (1.f / HD) + EPSV) * w[i];

    __shared__ float sm[HD];
    sm[i] = n;
    __syncthreads();
    float rot = (i < 64) ? -sm[i + 64] : sm[i - 64];
    float r = (n * cs[(size_t)t * HD + i] + rot * sn[(size_t)t * HD + i]) * outscale;
    out16[oidx] = __float2half_rn(r);
}

extern "C" void kernel_launch(void* const* d_in, const int* in_sizes, int n_in,
                              void* d_out, int out_size)
{
    const float* x    = (const float*)d_in[0];
    const float* cosv = (const float*)d_in[1];
    const float* sinv = (const float*)d_in[2];
    const float* wq   = (const float*)d_in[4];
    const float* bq   = (const float*)d_in[5];
    const float* wk   = (const float*)d_in[6];
    const float* bk   = (const float*)d_in[7];
    const float* wv   = (const float*)d_in[8];
    const float* bv   = (const float*)d_in[9];
    const float* wo   = (const float*)d_in[10];
    const float* qw   = (const float*)d_in[11];
    const float* kw   = (const float*)d_in[12];
    const float* ln1  = (const float*)d_in[13];
    const float* ln2  = (const float*)d_in[14];
    const float* wg   = (const float*)d_in[15];
    const float* wu   = (const float*)d_in[16];
    const float* wd   = (const float*)d_in[17];
    float* out = (float*)d_out;

    float* s = nullptr;
    cudaGetSymbolAddress((void**)&s, g_scratch);
    __half* hs = nullptr;
    cudaGetSymbolAddress((void**)&hs, g_hscratch);

    float* scores = s + OFF_SCORES;
    float* x2     = s + OFF_X2;
    float* biasc  = s + OFF_BIAS;

    __half* hwqkv  = hs + HW_QKV;
    __half* hwo    = hs + HW_O;
    __half* hwg    = hs + HW_G;
    __half* hwu    = hs + HW_U;
    __half* hwd    = hs + HW_D;
    __half* h16    = hs + H_H16;
    __half* qkv16  = hs + H_QKV16;
    __half* q16    = hs + H_Q16;
    __half* k16    = hs + H_K16;
    __half* p16    = hs + H_P16;
    __half* at16   = hs + H_ATTN16;
    __half* g16    = hs + H_G16;

    cudaFuncSetAttribute(casgemm_tn<1, 1>, cudaFuncAttributeMaxDynamicSharedMemorySize, CAS_SMEM_BYTES);
    cudaFuncSetAttribute(casgemm_tn<2, 0>, cudaFuncAttributeMaxDynamicSharedMemorySize, CAS_SMEM_BYTES);
    cudaFuncSetAttribute(casgemm_tn<0, 1>, cudaFuncAttributeMaxDynamicSharedMemorySize, CAS_SMEM_BYTES);
    cudaFuncSetAttribute(casgemm_tn<3, 1>, cudaFuncAttributeMaxDynamicSharedMemorySize, CAS_SMEM_BYTES);
    cudaFuncSetAttribute(hpv_cas,          cudaFuncAttributeMaxDynamicSharedMemorySize, PV_SMEM_BYTES);

    // 0. weights fp32 -> fp16 (QKV concatenated)
    f2h_kernel<<<2048, 256>>>(wq, hwqkv,                       HIDN * HIDN);
    f2h_kernel<<<1024, 256>>>(wk, hwqkv + HIDN * HIDN,         KVW * HIDN);
    f2h_kernel<<<1024, 256>>>(wv, hwqkv + (HIDN + KVW) * HIDN, KVW * HIDN);
    f2h_kernel<<<2048, 256>>>(wo, hwo, HIDN * HIDN);
    f2h_kernel<<<4096, 256>>>(wg, hwg, FF * HIDN);
    f2h_kernel<<<4096, 256>>>(wu, hwu, FF * HIDN);
    f2h_kernel<<<4096, 256>>>(wd, hwd, HIDN * FF);
    bias_concat_kernel<<<12, 256>>>(bq, bk, bv, biasc);

    // 1. h16 = rmsnorm(x, ln1)
    rmsnorm_h_kernel<<<T_TOK, 256>>>(x, ln1, h16);

    // 2. fused QKV projection (+bias) -> fp16 qkv16
    casgemm_tn<1, 1><<<dim3(NQKV / 128, T_TOK / 128), 256, CAS_SMEM_BYTES>>>(
        h16, HIDN, hwqkv, HIDN, qkv16, NQKV, HIDN, biasc, nullptr, nullptr);

    // 3-4. per-head RMS + RoPE -> q16 (pre-scaled) / k16 ; V stays in qkv16
    head_rms_rope_h_kernel<<<dim3(T_TOK, NH),  HD>>>(qkv16, NQKV, 0,    qw, cosv, sinv, q16, HIDN, SCALE);
    head_rms_rope_h_kernel<<<dim3(T_TOK, NKV), HD>>>(qkv16, NQKV, HIDN, kw, cosv, sinv, k16, KVW, 1.0f);

    // 5. scores (lower triangle, analytic mask; scale pre-folded into q16)
    hscores<<<dim3(SEQ / BN, SEQ / BM, BATCH * NH), 256>>>(q16, k16, scores);

    // 6. softmax -> p16
    softmax_kernel<<<BATCH * NH * SEQ, 256>>>(scores, p16);

    // 7. attn16 = P @ V (cp.async, causal-trimmed; V in-place in qkv16)
    hpv_cas<<<dim3(1, SEQ / 128, BATCH * NH), 256, PV_SMEM_BYTES>>>(
        p16, qkv16 + HIDN + KVW, NQKV, at16);

    // 8. x2 = x + attn @ wo^T
    casgemm_tn<2, 0><<<dim3(HIDN / 128, T_TOK / 128), 256, CAS_SMEM_BYTES>>>(
        at16, HIDN, hwo, HIDN, x2, HIDN, HIDN, nullptr, x, nullptr);

    // 9. h16 = rmsnorm(x2, ln2)
    rmsnorm_h_kernel<<<T_TOK, 256>>>(x2, ln2, h16);

    // 10. gate -> g16 (fp16)
    casgemm_tn<0, 1><<<dim3(FF / 128, T_TOK / 128), 256, CAS_SMEM_BYTES>>>(
        h16, HIDN, hwg, HIDN, g16, FF, HIDN, nullptr, nullptr, nullptr);

    // 11. up + fused silu: g16 = silu(g16) * up (in place)
    casgemm_tn<3, 1><<<dim3(FF / 128, T_TOK / 128), 256, CAS_SMEM_BYTES>>>(
        h16, HIDN, hwu, HIDN, g16, FF, HIDN, nullptr, nullptr, g16);

    // 12. out = x2 + g16 @ wd^T
    casgemm_tn<2, 0><<<dim3(HIDN / 128, T_TOK / 128), 256, CAS_SMEM_BYTES>>>(
        g16, FF, hwd, FF, out, HIDN, FF, nullptr, x2, nullptr);
}